// round 12
// baseline (speedup 1.0000x reference)
#include <cuda_runtime.h>
#include <cuda_bf16.h>
#include <cstdint>

// Problem shape (fixed for this bench)
#define Bdim 128
#define Tdim 784
#define Kdim 512   // K of branch GEMMs
#define Hdim 512   // N of branch GEMMs
#define Odim 10
#define Mdim (Bdim * Tdim)   // 100352

// ---------------------------------------------------------------------------
// Scratch (device globals: allocation inside kernel_launch is forbidden)
// ---------------------------------------------------------------------------
__device__ float    g_d1[(size_t)Mdim * Hdim];
__device__ float    g_d2[(size_t)Mdim * Hdim];
__device__ uint32_t g_ballot[(size_t)Mdim * 16];   // 512 spikes -> 16 words per (b,t)
__device__ float    g_xt[(size_t)Kdim * Mdim];     // X transposed [K][M]
__device__ float    g_w1t[Kdim * Hdim];            // W1 transposed [K][N]
__device__ float    g_w2t[Kdim * Hdim];            // W2 transposed [K][N]

__device__ __forceinline__ uint32_t smem_u32(const void* p) {
    uint32_t a;
    asm("{ .reg .u64 t; cvta.to.shared.u64 t, %1; cvt.u32.u64 %0, t; }"
        : "=r"(a) : "l"(p));
    return a;
}

// ---------------------------------------------------------------------------
// Transpose: dst[C][R] = src[R][C]   (exact copy, bit-exact trivially)
// ---------------------------------------------------------------------------
__global__ void __launch_bounds__(256) transpose_kernel(
    const float* __restrict__ src, float* __restrict__ dst, int R, int C)
{
    __shared__ float tile[32][33];
    const int r0 = blockIdx.x * 32;
    const int c0 = blockIdx.y * 32;
    const int tx = threadIdx.x & 31;
    const int ty = threadIdx.x >> 5;   // 0..7
    #pragma unroll
    for (int j = 0; j < 4; j++)
        tile[ty + j * 8][tx] = src[(size_t)(r0 + ty + j * 8) * C + c0 + tx];
    __syncthreads();
    #pragma unroll
    for (int j = 0; j < 4; j++)
        dst[(size_t)(c0 + ty + j * 8) * R + r0 + tx] = tile[tx][ty + j * 8];
}

// ---------------------------------------------------------------------------
// Fused dual-branch GEMM: d1 = X@W1^T + b1 AND d2 = X@W2^T + b2 in one CTA.
//   A-fragments amortized over both branches: 0.75 B LDS per FMA.
//   Bit-exact fp32: ascending-k scalar IEEE FMA chain per output.
//   grid: (4, 784): n0 = x*128, m0 = y*128. CTA tile 128m x 128n x 2 branches.
//   K in 32 chunks of BK=16; cp.async from pre-transposed operands into
//   double-buffered k-major SMEM; plain-C register fragment double-buffering.
// ---------------------------------------------------------------------------
#define BK 16
#define LDSX 132                      // floats per k-row (128 data + 4 pad)
#define TBUF (BK * LDSX)              // 2112 floats per stage per matrix
#define SMEM_BYTES (6 * TBUF * 4)     // X[2] + W1[2] + W2[2] = 50688 B

#define CP16(s, g) \
    asm volatile("cp.async.cg.shared.global [%0], [%1], 16;" :: "r"(s), "l"(g) : "memory")

__global__ void __launch_bounds__(256, 1) gemm_fused_kernel(
    const float* __restrict__ Xt,
    const float* __restrict__ W1t, const float* __restrict__ b1,
    const float* __restrict__ W2t, const float* __restrict__ b2)
{
    extern __shared__ float sm[];
    // stage p: Xs = sm + p*TBUF; W1s = sm + (2+p)*TBUF; W2s = sm + (4+p)*TBUF
    const uint32_t smbase = smem_u32(sm);

    const int tid  = threadIdx.x;
    const int lane = tid & 31;
    const int wid  = tid >> 5;
    const int mloc = (wid & 3) * 32 + (lane >> 3) * 8;   // thread row base
    const int nloc = (wid >> 2) * 64 + (lane & 7) * 8;   // thread col base

    const int n0 = blockIdx.x * 128;
    const int m0 = blockIdx.y * 128;

    // cp.async mapping: row = tid>>4 (0..15), cols (tid&15)*4 and +64 floats
    const int crow = tid >> 4;
    const int ccol = (tid & 15) * 4;
    const uint32_t cp_soff = (uint32_t)(crow * LDSX + ccol) * 4;
    const float* xgp  = Xt  + (size_t)crow * Mdim + m0 + ccol;
    const float* w1gp = W1t + (size_t)crow * Hdim + n0 + ccol;
    const float* w2gp = W2t + (size_t)crow * Hdim + n0 + ccol;

#define CP_CHUNK(c, p) do {                                                 \
        const size_t _kx = (size_t)(c) * BK * Mdim;                         \
        const size_t _kw = (size_t)(c) * BK * Hdim;                         \
        const uint32_t _sx = smbase + ((p) * TBUF) * 4 + cp_soff;           \
        const uint32_t _s1 = smbase + ((2 + (p)) * TBUF) * 4 + cp_soff;     \
        const uint32_t _s2 = smbase + ((4 + (p)) * TBUF) * 4 + cp_soff;     \
        CP16(_sx,       xgp  + _kx);                                        \
        CP16(_sx + 256, xgp  + _kx + 64);                                   \
        CP16(_s1,       w1gp + _kw);                                        \
        CP16(_s1 + 256, w1gp + _kw + 64);                                   \
        CP16(_s2,       w2gp + _kw);                                        \
        CP16(_s2 + 256, w2gp + _kw + 64);                                   \
        asm volatile("cp.async.commit_group;" ::: "memory");                \
    } while (0)

#define LDFRAG(buf, kk) do {                                                \
        const float* _xr = xb  + (kk) * LDSX + mloc;                        \
        const float* _w1 = w1b + (kk) * LDSX + nloc;                        \
        const float* _w2 = w2b + (kk) * LDSX + nloc;                        \
        *(float4*)&fa[buf][0] = *(const float4*)_xr;                        \
        *(float4*)&fa[buf][4] = *(const float4*)(_xr + 4);                  \
        *(float4*)&f1[buf][0] = *(const float4*)_w1;                        \
        *(float4*)&f1[buf][4] = *(const float4*)(_w1 + 4);                  \
        *(float4*)&f2[buf][0] = *(const float4*)_w2;                        \
        *(float4*)&f2[buf][4] = *(const float4*)(_w2 + 4);                  \
    } while (0)

    float acc1[8][8], acc2[8][8];
    #pragma unroll
    for (int i = 0; i < 8; i++)
        #pragma unroll
        for (int j = 0; j < 8; j++) { acc1[i][j] = 0.f; acc2[i][j] = 0.f; }

    CP_CHUNK(0, 0);
    CP_CHUNK(1, 1);

    for (int c = 0; c < 32; ++c) {
        const int p = c & 1;
        if (c < 31) asm volatile("cp.async.wait_group 1;" ::: "memory");
        else        asm volatile("cp.async.wait_group 0;" ::: "memory");
        __syncthreads();

        const float* xb  = sm + p * TBUF;
        const float* w1b = sm + (2 + p) * TBUF;
        const float* w2b = sm + (4 + p) * TBUF;

        float fa[2][8], f1[2][8], f2[2][8];
        LDFRAG(0, 0);
        #pragma unroll
        for (int kk = 0; kk < BK; kk++) {
            const int cur = kk & 1;
            if (kk < BK - 1) LDFRAG(cur ^ 1, kk + 1);
            #pragma unroll
            for (int i = 0; i < 8; i++)
                #pragma unroll
                for (int j = 0; j < 8; j++) {
                    acc1[i][j] = fmaf(fa[cur][i], f1[cur][j], acc1[i][j]);
                    acc2[i][j] = fmaf(fa[cur][i], f2[cur][j], acc2[i][j]);
                }
        }

        __syncthreads();                    // all reads of buffer p done
        if (c < 30) CP_CHUNK(c + 2, p);     // refill buffer p for chunk c+2
    }

    // Epilogue: add bias, store both branches
    {
        const int nb = n0 + nloc;
        float bs1[8], bs2[8];
        #pragma unroll
        for (int j = 0; j < 8; j++) { bs1[j] = b1[nb + j]; bs2[j] = b2[nb + j]; }

        #pragma unroll
        for (int i = 0; i < 8; i++) {
            const int m = m0 + mloc + i;
            float* d1p = g_d1 + (size_t)m * Hdim + nb;
            float* d2p = g_d2 + (size_t)m * Hdim + nb;
            *(float4*)d1p = make_float4(acc1[i][0] + bs1[0], acc1[i][1] + bs1[1],
                                        acc1[i][2] + bs1[2], acc1[i][3] + bs1[3]);
            *(float4*)(d1p + 4) = make_float4(acc1[i][4] + bs1[4], acc1[i][5] + bs1[5],
                                              acc1[i][6] + bs1[6], acc1[i][7] + bs1[7]);
            *(float4*)d2p = make_float4(acc2[i][0] + bs2[0], acc2[i][1] + bs2[1],
                                        acc2[i][2] + bs2[2], acc2[i][3] + bs2[3]);
            *(float4*)(d2p + 4) = make_float4(acc2[i][4] + bs2[4], acc2[i][5] + bs2[5],
                                              acc2[i][6] + bs2[6], acc2[i][7] + bs2[7]);
        }
    }
}

// ---------------------------------------------------------------------------
// Kernel B: sequential LIF scan, software-pipelined in batches of 8 timesteps.
// ---------------------------------------------------------------------------
__device__ __forceinline__ float sigmoidf(float x) { return 1.f / (1.f + expf(-x)); }

#define SB 8                          // timestep batch (784 = 8*98)

__global__ void __launch_bounds__(256) scan_kernel(
    const float* __restrict__ tau_m,
    const float* __restrict__ tau_n1,
    const float* __restrict__ tau_n2,
    const float* __restrict__ mem0,
    const float* __restrict__ spike0)
{
    const int tid = blockIdx.x * blockDim.x + threadIdx.x;
    const int b = tid / Hdim;
    const int h = tid - b * Hdim;
    const int lane = threadIdx.x & 31;

    const float alpha = sigmoidf(tau_m[h]);
    const float beta1 = sigmoidf(tau_n1[h]);
    const float beta2 = sigmoidf(tau_n2[h]);
    const float om_a = 1.f - alpha, om_b1 = 1.f - beta1, om_b2 = 1.f - beta2;

    float mem = mem0[tid];
    float spk = spike0[tid];
    float d1 = 0.f, d2 = 0.f;

    size_t base = ((size_t)b * Tdim) * Hdim + h;
    size_t bidx = ((size_t)b * Tdim) * 16 + (h >> 5);
    const float* __restrict__ D1 = g_d1;
    const float* __restrict__ D2 = g_d2;

    float pd1[SB], pd2[SB];
    #pragma unroll
    for (int j = 0; j < SB; j++) {
        pd1[j] = __ldcs(D1 + base + (size_t)j * Hdim);
        pd2[j] = __ldcs(D2 + base + (size_t)j * Hdim);
    }

    for (int tb = 0; tb < Tdim / SB; tb++) {
        float nd1[SB], nd2[SB];
        if (tb < Tdim / SB - 1) {
            #pragma unroll
            for (int j = 0; j < SB; j++) {
                nd1[j] = __ldcs(D1 + base + (size_t)(SB + j) * Hdim);
                nd2[j] = __ldcs(D2 + base + (size_t)(SB + j) * Hdim);
            }
        }
        #pragma unroll
        for (int j = 0; j < SB; j++) {
            float d1t = pd1[j];
            float d2t = pd2[j];
            d1 = beta1 * d1 + om_b1 * d1t;
            d2 = beta2 * d2 + om_b2 * d2t;
            mem = mem * alpha + om_a * (d1 + d2) - spk;   // V_TH = 1
            spk = (mem > 1.f) ? 1.f : 0.f;
            unsigned bal = __ballot_sync(0xffffffffu, mem > 1.f);
            if (lane == 0) g_ballot[bidx + (size_t)j * 16] = bal;
        }
        #pragma unroll
        for (int j = 0; j < SB; j++) { pd1[j] = nd1[j]; pd2[j] = nd2[j]; }
        base += (size_t)SB * Hdim;
        bidx += (size_t)SB * 16;
    }
}

// ---------------------------------------------------------------------------
// Kernel C: readout from spike ballots (8 rows per warp).
// ---------------------------------------------------------------------------
#define ROWS_PER_WARP 8

__global__ void __launch_bounds__(256) readout_kernel(
    const float* __restrict__ Wr,
    const float* __restrict__ br,
    float* __restrict__ Out)
{
    __shared__ float WrS[Odim * Hdim];   // 20 KB
    __shared__ float brS[Odim];
    for (int i = threadIdx.x; i < Odim * Hdim; i += blockDim.x) WrS[i] = Wr[i];
    if (threadIdx.x < Odim) brS[threadIdx.x] = br[threadIdx.x];
    __syncthreads();

    const int warp = threadIdx.x >> 5;
    const int lane = threadIdx.x & 31;
    const int mbase = (blockIdx.x * 8 + warp) * ROWS_PER_WARP;

    for (int g = 0; g < ROWS_PER_WARP; g++) {
        const int m = mbase + g;

        const uint32_t* gb = g_ballot + (size_t)m * 16;
        uint32_t w = (lane < 16) ? gb[lane] : 0u;

        float acc[Odim];
        #pragma unroll
        for (int o = 0; o < Odim; o++) acc[o] = 0.f;

        #pragma unroll
        for (int j = 0; j < 16; j++) {           // h = j*32 + lane (ascending)
            const uint32_t wj = __shfl_sync(0xffffffffu, w, j);
            const float s = ((wj >> lane) & 1u) ? 1.f : 0.f;
            const int hh = j * 32 + lane;
            #pragma unroll
            for (int o = 0; o < Odim; o++)
                acc[o] = fmaf(s, WrS[o * Hdim + hh], acc[o]);
        }

        #pragma unroll
        for (int o = 0; o < Odim; o++)
            #pragma unroll
            for (int d = 16; d; d >>= 1)
                acc[o] += __shfl_xor_sync(0xffffffffu, acc[o], d);

        if (lane == 0) {
            #pragma unroll
            for (int o = 0; o < Odim; o++)
                Out[(size_t)m * Odim + o] = acc[o] + brS[o];
        }
    }
}

// ---------------------------------------------------------------------------
// Launch
// ---------------------------------------------------------------------------
extern "C" void kernel_launch(void* const* d_in, const int* in_sizes, int n_in,
                              void* d_out, int out_size)
{
    const float* input_data = (const float*)d_in[0];
    const float* W1     = (const float*)d_in[1];
    const float* b1     = (const float*)d_in[2];
    const float* W2     = (const float*)d_in[3];
    const float* b2     = (const float*)d_in[4];
    const float* tau_m  = (const float*)d_in[5];
    const float* tau_n1 = (const float*)d_in[6];
    const float* tau_n2 = (const float*)d_in[7];
    const float* Wr     = (const float*)d_in[8];
    const float* br     = (const float*)d_in[9];
    const float* mem0   = (const float*)d_in[10];
    const float* spike0 = (const float*)d_in[11];
    float* out = (float*)d_out;

    (void)in_sizes; (void)n_in; (void)out_size;

    float *xt, *w1t, *w2t;
    cudaGetSymbolAddress((void**)&xt,  g_xt);
    cudaGetSymbolAddress((void**)&w1t, g_w1t);
    cudaGetSymbolAddress((void**)&w2t, g_w2t);

    // Pre-transpose operands (bit-exact copies)
    transpose_kernel<<<dim3(Mdim / 32, Kdim / 32), 256>>>(input_data, xt, Mdim, Kdim);
    transpose_kernel<<<dim3(Hdim / 32, Kdim / 32), 256>>>(W1, w1t, Hdim, Kdim);
    transpose_kernel<<<dim3(Hdim / 32, Kdim / 32), 256>>>(W2, w2t, Hdim, Kdim);

    cudaFuncSetAttribute(gemm_fused_kernel,
                         cudaFuncAttributeMaxDynamicSharedMemorySize, SMEM_BYTES);

    gemm_fused_kernel<<<dim3(Hdim / 128, Mdim / 128), 256, SMEM_BYTES>>>(
        xt, w1t, b1, w2t, b2);

    scan_kernel<<<(Bdim * Hdim) / 256, 256>>>(tau_m, tau_n1, tau_n2, mem0, spike0);

    readout_kernel<<<Mdim / (8 * ROWS_PER_WARP), 256>>>(Wr, br, out);
}

// round 13
// speedup vs baseline: 1.0077x; 1.0077x over previous
#include <cuda_runtime.h>
#include <cuda_bf16.h>
#include <cstdint>

// Problem shape (fixed for this bench)
#define Bdim 128
#define Tdim 784
#define Kdim 512   // K of branch GEMMs
#define Hdim 512   // N of branch GEMMs
#define Odim 10
#define Mdim (Bdim * Tdim)   // 100352

// ---------------------------------------------------------------------------
// Scratch (device globals: allocation inside kernel_launch is forbidden)
// ---------------------------------------------------------------------------
__device__ float    g_d1[(size_t)Mdim * Hdim];
__device__ float    g_d2[(size_t)Mdim * Hdim];
__device__ uint32_t g_ballot[(size_t)Mdim * 16];   // 512 spikes -> 16 words per (b,t)
__device__ float    g_xt[(size_t)Kdim * Mdim];     // X transposed [K][M]
__device__ float    g_w1t[Kdim * Hdim];            // W1 transposed [K][N]
__device__ float    g_w2t[Kdim * Hdim];            // W2 transposed [K][N]

__device__ __forceinline__ uint32_t smem_u32(const void* p) {
    uint32_t a;
    asm("{ .reg .u64 t; cvta.to.shared.u64 t, %1; cvt.u32.u64 %0, t; }"
        : "=r"(a) : "l"(p));
    return a;
}

// ---------------------------------------------------------------------------
// Transpose: dst[C][R] = src[R][C]   (exact copy, bit-exact trivially)
// ---------------------------------------------------------------------------
__global__ void __launch_bounds__(256) transpose_kernel(
    const float* __restrict__ src, float* __restrict__ dst, int R, int C)
{
    __shared__ float tile[32][33];
    const int r0 = blockIdx.x * 32;
    const int c0 = blockIdx.y * 32;
    const int tx = threadIdx.x & 31;
    const int ty = threadIdx.x >> 5;   // 0..7
    #pragma unroll
    for (int j = 0; j < 4; j++)
        tile[ty + j * 8][tx] = src[(size_t)(r0 + ty + j * 8) * C + c0 + tx];
    __syncthreads();
    #pragma unroll
    for (int j = 0; j < 4; j++)
        dst[(size_t)(c0 + ty + j * 8) * R + r0 + tx] = tile[tx][ty + j * 8];
}

// ---------------------------------------------------------------------------
// Fused dual-branch GEMM: d1 = X@W1^T + b1 AND d2 = X@W2^T + b2 in one CTA.
//   Bit-exact fp32: ascending-k scalar IEEE FMA chain per output.
//   grid: (4, 784): n0 = x*128, m0 = y*128. CTA tile 128m x 128n x 2 branches.
//   K in 16 chunks of BK=32; 3-stage cp.async pipeline, ONE barrier per chunk.
// ---------------------------------------------------------------------------
#define BK 32
#define LDSX 132                      // floats per k-row (128 data + 4 pad)
#define TBUF (BK * LDSX)              // 4224 floats per stage per matrix
#define NCHUNK (Kdim / BK)            // 16
#define SMEM_BYTES (9 * TBUF * 4)     // 3 stages x 3 matrices = 152064 B

#define CP16(s, g) \
    asm volatile("cp.async.cg.shared.global [%0], [%1], 16;" :: "r"(s), "l"(g) : "memory")

__global__ void __launch_bounds__(256, 1) gemm_fused_kernel(
    const float* __restrict__ Xt,
    const float* __restrict__ W1t, const float* __restrict__ b1,
    const float* __restrict__ W2t, const float* __restrict__ b2)
{
    extern __shared__ float sm[];
    // X stages at sm + p*TBUF, W1 at sm + (3+p)*TBUF, W2 at sm + (6+p)*TBUF
    const uint32_t smbase = smem_u32(sm);

    const int tid  = threadIdx.x;
    const int lane = tid & 31;
    const int wid  = tid >> 5;
    const int mloc = (wid & 3) * 32 + (lane >> 3) * 8;   // thread row base
    const int nloc = (wid >> 2) * 64 + (lane & 7) * 8;   // thread col base

    const int n0 = blockIdx.x * 128;
    const int m0 = blockIdx.y * 128;

    // cp.async mapping: 32 rows x 32 float4 per matrix per chunk;
    // thread covers rows (tid>>5)+8j, float4-col tid&31, j = 0..3.
    const int crow = tid >> 5;            // 0..7
    const int ccol = (tid & 31) * 4;      // float col
    const float* xgp  = Xt  + (size_t)crow * Mdim + m0 + ccol;
    const float* w1gp = W1t + (size_t)crow * Hdim + n0 + ccol;
    const float* w2gp = W2t + (size_t)crow * Hdim + n0 + ccol;

#define CP_CHUNK(c, p) do {                                                  \
        _Pragma("unroll")                                                    \
        for (int _j = 0; _j < 4; _j++) {                                     \
            const int _row = crow + _j * 8;  /* row within chunk (implicit via ptr) */ \
            (void)_row;                                                      \
            const size_t _kx = ((size_t)(c) * BK + _j * 8) * Mdim;           \
            const size_t _kw = ((size_t)(c) * BK + _j * 8) * Hdim;           \
            const uint32_t _so = ((_j * 8 + crow) * LDSX + ccol) * 4;        \
            CP16(smbase + ((p) * TBUF) * 4 + _so,       xgp  + _kx);         \
            CP16(smbase + ((3 + (p)) * TBUF) * 4 + _so, w1gp + _kw);         \
            CP16(smbase + ((6 + (p)) * TBUF) * 4 + _so, w2gp + _kw);         \
        }                                                                    \
        asm volatile("cp.async.commit_group;" ::: "memory");                 \
    } while (0)

#define LDFRAG(buf, kk) do {                                                 \
        const float* _xr = xb  + (kk) * LDSX + mloc;                         \
        const float* _w1 = w1b + (kk) * LDSX + nloc;                         \
        const float* _w2 = w2b + (kk) * LDSX + nloc;                         \
        *(float4*)&fa[buf][0] = *(const float4*)_xr;                         \
        *(float4*)&fa[buf][4] = *(const float4*)(_xr + 4);                   \
        *(float4*)&f1[buf][0] = *(const float4*)_w1;                         \
        *(float4*)&f1[buf][4] = *(const float4*)(_w1 + 4);                   \
        *(float4*)&f2[buf][0] = *(const float4*)_w2;                         \
        *(float4*)&f2[buf][4] = *(const float4*)(_w2 + 4);                   \
    } while (0)

    float acc1[8][8], acc2[8][8];
    #pragma unroll
    for (int i = 0; i < 8; i++)
        #pragma unroll
        for (int j = 0; j < 8; j++) { acc1[i][j] = 0.f; acc2[i][j] = 0.f; }

    CP_CHUNK(0, 0);
    CP_CHUNK(1, 1);

    for (int c = 0; c < NCHUNK; ++c) {
        const int p = c % 3;
        if (c < NCHUNK - 1) asm volatile("cp.async.wait_group 1;" ::: "memory");
        else                asm volatile("cp.async.wait_group 0;" ::: "memory");
        __syncthreads();
        // Refill stage (c+2)%3: it was last read at chunk c-1, which every
        // thread finished before the barrier above.
        if (c < NCHUNK - 2) CP_CHUNK(c + 2, (c + 2) % 3);

        const float* xb  = sm + p * TBUF;
        const float* w1b = sm + (3 + p) * TBUF;
        const float* w2b = sm + (6 + p) * TBUF;

        float fa[2][8], f1[2][8], f2[2][8];
        LDFRAG(0, 0);
        #pragma unroll
        for (int kk = 0; kk < BK; kk++) {
            const int cur = kk & 1;
            if (kk < BK - 1) LDFRAG(cur ^ 1, kk + 1);
            #pragma unroll
            for (int i = 0; i < 8; i++)
                #pragma unroll
                for (int j = 0; j < 8; j++) {
                    acc1[i][j] = fmaf(fa[cur][i], f1[cur][j], acc1[i][j]);
                    acc2[i][j] = fmaf(fa[cur][i], f2[cur][j], acc2[i][j]);
                }
        }
        // no trailing barrier: next iteration's barrier protects stage reuse
    }

    // Epilogue: add bias, store both branches
    {
        const int nb = n0 + nloc;
        float bs1[8], bs2[8];
        #pragma unroll
        for (int j = 0; j < 8; j++) { bs1[j] = b1[nb + j]; bs2[j] = b2[nb + j]; }

        #pragma unroll
        for (int i = 0; i < 8; i++) {
            const int m = m0 + mloc + i;
            float* d1p = g_d1 + (size_t)m * Hdim + nb;
            float* d2p = g_d2 + (size_t)m * Hdim + nb;
            *(float4*)d1p = make_float4(acc1[i][0] + bs1[0], acc1[i][1] + bs1[1],
                                        acc1[i][2] + bs1[2], acc1[i][3] + bs1[3]);
            *(float4*)(d1p + 4) = make_float4(acc1[i][4] + bs1[4], acc1[i][5] + bs1[5],
                                              acc1[i][6] + bs1[6], acc1[i][7] + bs1[7]);
            *(float4*)d2p = make_float4(acc2[i][0] + bs2[0], acc2[i][1] + bs2[1],
                                        acc2[i][2] + bs2[2], acc2[i][3] + bs2[3]);
            *(float4*)(d2p + 4) = make_float4(acc2[i][4] + bs2[4], acc2[i][5] + bs2[5],
                                              acc2[i][6] + bs2[6], acc2[i][7] + bs2[7]);
        }
    }
}

// ---------------------------------------------------------------------------
// Kernel B: sequential LIF scan, software-pipelined in batches of 8 timesteps.
// ---------------------------------------------------------------------------
__device__ __forceinline__ float sigmoidf(float x) { return 1.f / (1.f + expf(-x)); }

#define SB 8                          // timestep batch (784 = 8*98)

__global__ void __launch_bounds__(256) scan_kernel(
    const float* __restrict__ tau_m,
    const float* __restrict__ tau_n1,
    const float* __restrict__ tau_n2,
    const float* __restrict__ mem0,
    const float* __restrict__ spike0)
{
    const int tid = blockIdx.x * blockDim.x + threadIdx.x;
    const int b = tid / Hdim;
    const int h = tid - b * Hdim;
    const int lane = threadIdx.x & 31;

    const float alpha = sigmoidf(tau_m[h]);
    const float beta1 = sigmoidf(tau_n1[h]);
    const float beta2 = sigmoidf(tau_n2[h]);
    const float om_a = 1.f - alpha, om_b1 = 1.f - beta1, om_b2 = 1.f - beta2;

    float mem = mem0[tid];
    float spk = spike0[tid];
    float d1 = 0.f, d2 = 0.f;

    size_t base = ((size_t)b * Tdim) * Hdim + h;
    size_t bidx = ((size_t)b * Tdim) * 16 + (h >> 5);
    const float* __restrict__ D1 = g_d1;
    const float* __restrict__ D2 = g_d2;

    float pd1[SB], pd2[SB];
    #pragma unroll
    for (int j = 0; j < SB; j++) {
        pd1[j] = __ldcs(D1 + base + (size_t)j * Hdim);
        pd2[j] = __ldcs(D2 + base + (size_t)j * Hdim);
    }

    for (int tb = 0; tb < Tdim / SB; tb++) {
        float nd1[SB], nd2[SB];
        if (tb < Tdim / SB - 1) {
            #pragma unroll
            for (int j = 0; j < SB; j++) {
                nd1[j] = __ldcs(D1 + base + (size_t)(SB + j) * Hdim);
                nd2[j] = __ldcs(D2 + base + (size_t)(SB + j) * Hdim);
            }
        }
        #pragma unroll
        for (int j = 0; j < SB; j++) {
            float d1t = pd1[j];
            float d2t = pd2[j];
            d1 = beta1 * d1 + om_b1 * d1t;
            d2 = beta2 * d2 + om_b2 * d2t;
            mem = mem * alpha + om_a * (d1 + d2) - spk;   // V_TH = 1
            spk = (mem > 1.f) ? 1.f : 0.f;
            unsigned bal = __ballot_sync(0xffffffffu, mem > 1.f);
            if (lane == 0) g_ballot[bidx + (size_t)j * 16] = bal;
        }
        #pragma unroll
        for (int j = 0; j < SB; j++) { pd1[j] = nd1[j]; pd2[j] = nd2[j]; }
        base += (size_t)SB * Hdim;
        bidx += (size_t)SB * 16;
    }
}

// ---------------------------------------------------------------------------
// Kernel C: readout from spike ballots (8 rows per warp).
// ---------------------------------------------------------------------------
#define ROWS_PER_WARP 8

__global__ void __launch_bounds__(256) readout_kernel(
    const float* __restrict__ Wr,
    const float* __restrict__ br,
    float* __restrict__ Out)
{
    __shared__ float WrS[Odim * Hdim];   // 20 KB
    __shared__ float brS[Odim];
    for (int i = threadIdx.x; i < Odim * Hdim; i += blockDim.x) WrS[i] = Wr[i];
    if (threadIdx.x < Odim) brS[threadIdx.x] = br[threadIdx.x];
    __syncthreads();

    const int warp = threadIdx.x >> 5;
    const int lane = threadIdx.x & 31;
    const int mbase = (blockIdx.x * 8 + warp) * ROWS_PER_WARP;

    for (int g = 0; g < ROWS_PER_WARP; g++) {
        const int m = mbase + g;

        const uint32_t* gb = g_ballot + (size_t)m * 16;
        uint32_t w = (lane < 16) ? gb[lane] : 0u;

        float acc[Odim];
        #pragma unroll
        for (int o = 0; o < Odim; o++) acc[o] = 0.f;

        #pragma unroll
        for (int j = 0; j < 16; j++) {           // h = j*32 + lane (ascending)
            const uint32_t wj = __shfl_sync(0xffffffffu, w, j);
            const float s = ((wj >> lane) & 1u) ? 1.f : 0.f;
            const int hh = j * 32 + lane;
            #pragma unroll
            for (int o = 0; o < Odim; o++)
                acc[o] = fmaf(s, WrS[o * Hdim + hh], acc[o]);
        }

        #pragma unroll
        for (int o = 0; o < Odim; o++)
            #pragma unroll
            for (int d = 16; d; d >>= 1)
                acc[o] += __shfl_xor_sync(0xffffffffu, acc[o], d);

        if (lane == 0) {
            #pragma unroll
            for (int o = 0; o < Odim; o++)
                Out[(size_t)m * Odim + o] = acc[o] + brS[o];
        }
    }
}

// ---------------------------------------------------------------------------
// Launch
// ---------------------------------------------------------------------------
extern "C" void kernel_launch(void* const* d_in, const int* in_sizes, int n_in,
                              void* d_out, int out_size)
{
    const float* input_data = (const float*)d_in[0];
    const float* W1     = (const float*)d_in[1];
    const float* b1     = (const float*)d_in[2];
    const float* W2     = (const float*)d_in[3];
    const float* b2     = (const float*)d_in[4];
    const float* tau_m  = (const float*)d_in[5];
    const float* tau_n1 = (const float*)d_in[6];
    const float* tau_n2 = (const float*)d_in[7];
    const float* Wr     = (const float*)d_in[8];
    const float* br     = (const float*)d_in[9];
    const float* mem0   = (const float*)d_in[10];
    const float* spike0 = (const float*)d_in[11];
    float* out = (float*)d_out;

    (void)in_sizes; (void)n_in; (void)out_size;

    float *xt, *w1t, *w2t;
    cudaGetSymbolAddress((void**)&xt,  g_xt);
    cudaGetSymbolAddress((void**)&w1t, g_w1t);
    cudaGetSymbolAddress((void**)&w2t, g_w2t);

    // Pre-transpose operands (bit-exact copies)
    transpose_kernel<<<dim3(Mdim / 32, Kdim / 32), 256>>>(input_data, xt, Mdim, Kdim);
    transpose_kernel<<<dim3(Hdim / 32, Kdim / 32), 256>>>(W1, w1t, Hdim, Kdim);
    transpose_kernel<<<dim3(Hdim / 32, Kdim / 32), 256>>>(W2, w2t, Hdim, Kdim);

    cudaFuncSetAttribute(gemm_fused_kernel,
                         cudaFuncAttributeMaxDynamicSharedMemorySize, SMEM_BYTES);

    gemm_fused_kernel<<<dim3(Hdim / 128, Mdim / 128), 256, SMEM_BYTES>>>(
        xt, w1t, b1, w2t, b2);

    scan_kernel<<<(Bdim * Hdim) / 256, 256>>>(tau_m, tau_n1, tau_n2, mem0, spike0);

    readout_kernel<<<Mdim / (8 * ROWS_PER_WARP), 256>>>(Wr, br, out);
}

// round 14
// speedup vs baseline: 1.0099x; 1.0022x over previous
#include <cuda_runtime.h>
#include <cuda_bf16.h>
#include <cstdint>

// Problem shape (fixed for this bench)
#define Bdim 128
#define Tdim 784
#define Kdim 512   // K of branch GEMMs
#define Hdim 512   // N of branch GEMMs
#define Odim 10
#define Mdim (Bdim * Tdim)   // 100352

// ---------------------------------------------------------------------------
// Scratch (device globals: allocation inside kernel_launch is forbidden)
// ---------------------------------------------------------------------------
__device__ float    g_d1[(size_t)Mdim * Hdim];
__device__ float    g_d2[(size_t)Mdim * Hdim];
__device__ uint32_t g_ballot[(size_t)Mdim * 16];   // 512 spikes -> 16 words per (b,t)
__device__ float    g_w1t[Kdim * Hdim];            // W1 transposed [K][N]
__device__ float    g_w2t[Kdim * Hdim];            // W2 transposed [K][N]

__device__ __forceinline__ uint32_t smem_u32(const void* p) {
    uint32_t a;
    asm("{ .reg .u64 t; cvta.to.shared.u64 t, %1; cvt.u32.u64 %0, t; }"
        : "=r"(a) : "l"(p));
    return a;
}

// ---------------------------------------------------------------------------
// Transpose: dst[C][R] = src[R][C]  (used only for W1/W2 — 1 MB each)
// ---------------------------------------------------------------------------
__global__ void __launch_bounds__(256) transpose_w_kernel(
    const float* __restrict__ W1, const float* __restrict__ W2)
{
    __shared__ float tile[32][33];
    const float* src = blockIdx.z ? W2 : W1;
    float* dst;
    { float* p; p = blockIdx.z ? g_w2t : g_w1t; dst = p; }
    const int r0 = blockIdx.x * 32;
    const int c0 = blockIdx.y * 32;
    const int tx = threadIdx.x & 31;
    const int ty = threadIdx.x >> 5;   // 0..7
    #pragma unroll
    for (int j = 0; j < 4; j++)
        tile[ty + j * 8][tx] = src[(size_t)(r0 + ty + j * 8) * Kdim + c0 + tx];
    __syncthreads();
    #pragma unroll
    for (int j = 0; j < 4; j++)
        dst[(size_t)(c0 + ty + j * 8) * Hdim + r0 + tx] = tile[tx][ty + j * 8];
}

// ---------------------------------------------------------------------------
// Fused dual-branch GEMM: d1 = X@W1^T + b1 AND d2 = X@W2^T + b2 in one CTA.
//   Bit-exact fp32: ascending-k scalar IEEE FMA chain per output.
//   X staged in registers (row-major LDG) + transposing STS (no pre-transpose).
//   W1/W2 via cp.async from pre-transposed copies.
//   grid: (4, 784): n0 = x*128, m0 = y*128. CTA tile 128m x 128n x 2 branches.
//   K in 32 chunks of BK=16, 2-stage double buffering.
// ---------------------------------------------------------------------------
#define BK 16
#define LDSX 132                      // floats per k-row (128 data + 4 pad)
#define XBUF (BK * LDSX)              // 2112 floats per stage per matrix
#define NCHUNK (Kdim / BK)            // 32
#define SMEM_BYTES (6 * XBUF * 4)     // 2 stages x (X + W1 + W2) = 50688 B

#define CP16(s, g) \
    asm volatile("cp.async.cg.shared.global [%0], [%1], 16;" :: "r"(s), "l"(g) : "memory")

__global__ void __launch_bounds__(256, 1) gemm_fused_kernel(
    const float* __restrict__ X,
    const float* __restrict__ W1t, const float* __restrict__ b1,
    const float* __restrict__ W2t, const float* __restrict__ b2)
{
    extern __shared__ float sm[];
    float* Xs  = sm;                  // [2][BK][LDSX]  Xs[k][m]
    float* W1s = sm + 2 * XBUF;       // [2][BK][LDSX]  W1s[k][n]
    float* W2s = sm + 4 * XBUF;       // [2][BK][LDSX]  W2s[k][n]
    const uint32_t smbase = smem_u32(sm);

    const int tid  = threadIdx.x;
    const int lane = tid & 31;
    const int wid  = tid >> 5;
    const int mloc = (wid & 3) * 32 + (lane >> 3) * 8;   // thread row base
    const int nloc = (wid >> 2) * 64 + (lane & 7) * 8;   // thread col base

    const int n0 = blockIdx.x * 128;
    const int m0 = blockIdx.y * 128;

    // X loader mapping (row-major, coalesced): rows tid>>2 (+64), cols (tid&3)*4
    const int lrow = tid >> 2;
    const int lcol = (tid & 3) * 4;
    const float* xg = X + (size_t)(m0 + lrow) * Kdim + lcol;

    // W cp.async mapping: k-row = tid>>4 (0..15), float cols (tid&15)*4 and +64
    const int crow = tid >> 4;
    const int ccol = (tid & 15) * 4;
    const uint32_t cp_soff = (uint32_t)(crow * LDSX + ccol) * 4;
    const float* w1gp = W1t + (size_t)crow * Hdim + n0 + ccol;
    const float* w2gp = W2t + (size_t)crow * Hdim + n0 + ccol;

#define LDG_X(c) do {                                                        \
        xr[0] = *(const float4*)(xg + (c) * BK);                             \
        xr[1] = *(const float4*)(xg + (size_t)64 * Kdim + (c) * BK);         \
    } while (0)

#define STS_X(p) do {                                                        \
        _Pragma("unroll")                                                    \
        for (int _r = 0; _r < 2; _r++) {                                     \
            const float _xv[4] = {xr[_r].x, xr[_r].y, xr[_r].z, xr[_r].w};   \
            _Pragma("unroll")                                                \
            for (int _u = 0; _u < 4; _u++)                                   \
                Xs[(p) * XBUF + (lcol + _u) * LDSX + lrow + _r * 64] = _xv[_u]; \
        }                                                                    \
    } while (0)

#define CP_W(c, p) do {                                                      \
        const size_t _kw = (size_t)(c) * BK * Hdim;                          \
        const uint32_t _s1 = smbase + ((2 + (p)) * XBUF) * 4 + cp_soff;      \
        const uint32_t _s2 = smbase + ((4 + (p)) * XBUF) * 4 + cp_soff;      \
        CP16(_s1,       w1gp + _kw);                                         \
        CP16(_s1 + 256, w1gp + _kw + 64);                                    \
        CP16(_s2,       w2gp + _kw);                                         \
        CP16(_s2 + 256, w2gp + _kw + 64);                                    \
        asm volatile("cp.async.commit_group;" ::: "memory");                 \
    } while (0)

#define LDFRAG(buf, kk) do {                                                 \
        const float* _xr = xb  + (kk) * LDSX + mloc;                         \
        const float* _w1 = w1b + (kk) * LDSX + nloc;                         \
        const float* _w2 = w2b + (kk) * LDSX + nloc;                         \
        *(float4*)&fa[buf][0] = *(const float4*)_xr;                         \
        *(float4*)&fa[buf][4] = *(const float4*)(_xr + 4);                   \
        *(float4*)&f1[buf][0] = *(const float4*)_w1;                         \
        *(float4*)&f1[buf][4] = *(const float4*)(_w1 + 4);                   \
        *(float4*)&f2[buf][0] = *(const float4*)_w2;                         \
        *(float4*)&f2[buf][4] = *(const float4*)(_w2 + 4);                   \
    } while (0)

    float acc1[8][8], acc2[8][8];
    #pragma unroll
    for (int i = 0; i < 8; i++)
        #pragma unroll
        for (int j = 0; j < 8; j++) { acc1[i][j] = 0.f; acc2[i][j] = 0.f; }

    float4 xr[2];

    // Prologue: chunk 0 fully staged; X of chunk 1 in registers.
    LDG_X(0);
    STS_X(0);
    CP_W(0, 0);
    LDG_X(1);

    for (int c = 0; c < NCHUNK; ++c) {
        const int p = c & 1;
        asm volatile("cp.async.wait_group 0;" ::: "memory");  // chunk c's W in
        __syncthreads();   // stage p complete (X STS'd last iter, W arrived)

        // Stage p^1 was fully consumed in iteration c-1 -> safe to refill.
        if (c + 1 < NCHUNK) {
            STS_X(p ^ 1);          // X chunk c+1 from registers
            CP_W(c + 1, p ^ 1);    // W chunk c+1 (lands during this compute)
        }
        if (c + 2 < NCHUNK) LDG_X(c + 2);   // X chunk c+2 into registers

        const float* xb  = Xs  + p * XBUF;
        const float* w1b = W1s + p * XBUF;
        const float* w2b = W2s + p * XBUF;

        float fa[2][8], f1[2][8], f2[2][8];
        LDFRAG(0, 0);
        #pragma unroll
        for (int kk = 0; kk < BK; kk++) {
            const int cur = kk & 1;
            if (kk < BK - 1) LDFRAG(cur ^ 1, kk + 1);
            #pragma unroll
            for (int i = 0; i < 8; i++)
                #pragma unroll
                for (int j = 0; j < 8; j++) {
                    acc1[i][j] = fmaf(fa[cur][i], f1[cur][j], acc1[i][j]);
                    acc2[i][j] = fmaf(fa[cur][i], f2[cur][j], acc2[i][j]);
                }
        }
        // next iteration's barrier protects stage reuse
    }

    // Epilogue: add bias, store both branches
    {
        const int nb = n0 + nloc;
        float bs1[8], bs2[8];
        #pragma unroll
        for (int j = 0; j < 8; j++) { bs1[j] = b1[nb + j]; bs2[j] = b2[nb + j]; }

        #pragma unroll
        for (int i = 0; i < 8; i++) {
            const int m = m0 + mloc + i;
            float* d1p = g_d1 + (size_t)m * Hdim + nb;
            float* d2p = g_d2 + (size_t)m * Hdim + nb;
            *(float4*)d1p = make_float4(acc1[i][0] + bs1[0], acc1[i][1] + bs1[1],
                                        acc1[i][2] + bs1[2], acc1[i][3] + bs1[3]);
            *(float4*)(d1p + 4) = make_float4(acc1[i][4] + bs1[4], acc1[i][5] + bs1[5],
                                              acc1[i][6] + bs1[6], acc1[i][7] + bs1[7]);
            *(float4*)d2p = make_float4(acc2[i][0] + bs2[0], acc2[i][1] + bs2[1],
                                        acc2[i][2] + bs2[2], acc2[i][3] + bs2[3]);
            *(float4*)(d2p + 4) = make_float4(acc2[i][4] + bs2[4], acc2[i][5] + bs2[5],
                                              acc2[i][6] + bs2[6], acc2[i][7] + bs2[7]);
        }
    }
}

// ---------------------------------------------------------------------------
// Kernel B: sequential LIF scan, software-pipelined in batches of 8 timesteps.
// ---------------------------------------------------------------------------
__device__ __forceinline__ float sigmoidf(float x) { return 1.f / (1.f + expf(-x)); }

#define SB 8                          // timestep batch (784 = 8*98)

__global__ void __launch_bounds__(256) scan_kernel(
    const float* __restrict__ tau_m,
    const float* __restrict__ tau_n1,
    const float* __restrict__ tau_n2,
    const float* __restrict__ mem0,
    const float* __restrict__ spike0)
{
    const int tid = blockIdx.x * blockDim.x + threadIdx.x;
    const int b = tid / Hdim;
    const int h = tid - b * Hdim;
    const int lane = threadIdx.x & 31;

    const float alpha = sigmoidf(tau_m[h]);
    const float beta1 = sigmoidf(tau_n1[h]);
    const float beta2 = sigmoidf(tau_n2[h]);
    const float om_a = 1.f - alpha, om_b1 = 1.f - beta1, om_b2 = 1.f - beta2;

    float mem = mem0[tid];
    float spk = spike0[tid];
    float d1 = 0.f, d2 = 0.f;

    size_t base = ((size_t)b * Tdim) * Hdim + h;
    size_t bidx = ((size_t)b * Tdim) * 16 + (h >> 5);
    const float* __restrict__ D1 = g_d1;
    const float* __restrict__ D2 = g_d2;

    float pd1[SB], pd2[SB];
    #pragma unroll
    for (int j = 0; j < SB; j++) {
        pd1[j] = __ldcs(D1 + base + (size_t)j * Hdim);
        pd2[j] = __ldcs(D2 + base + (size_t)j * Hdim);
    }

    for (int tb = 0; tb < Tdim / SB; tb++) {
        float nd1[SB], nd2[SB];
        if (tb < Tdim / SB - 1) {
            #pragma unroll
            for (int j = 0; j < SB; j++) {
                nd1[j] = __ldcs(D1 + base + (size_t)(SB + j) * Hdim);
                nd2[j] = __ldcs(D2 + base + (size_t)(SB + j) * Hdim);
            }
        }
        #pragma unroll
        for (int j = 0; j < SB; j++) {
            float d1t = pd1[j];
            float d2t = pd2[j];
            d1 = beta1 * d1 + om_b1 * d1t;
            d2 = beta2 * d2 + om_b2 * d2t;
            mem = mem * alpha + om_a * (d1 + d2) - spk;   // V_TH = 1
            spk = (mem > 1.f) ? 1.f : 0.f;
            unsigned bal = __ballot_sync(0xffffffffu, mem > 1.f);
            if (lane == 0) g_ballot[bidx + (size_t)j * 16] = bal;
        }
        #pragma unroll
        for (int j = 0; j < SB; j++) { pd1[j] = nd1[j]; pd2[j] = nd2[j]; }
        base += (size_t)SB * Hdim;
        bidx += (size_t)SB * 16;
    }
}

// ---------------------------------------------------------------------------
// Kernel C: readout from spike ballots (8 rows per warp).
// ---------------------------------------------------------------------------
#define ROWS_PER_WARP 8

__global__ void __launch_bounds__(256) readout_kernel(
    const float* __restrict__ Wr,
    const float* __restrict__ br,
    float* __restrict__ Out)
{
    __shared__ float WrS[Odim * Hdim];   // 20 KB
    __shared__ float brS[Odim];
    for (int i = threadIdx.x; i < Odim * Hdim; i += blockDim.x) WrS[i] = Wr[i];
    if (threadIdx.x < Odim) brS[threadIdx.x] = br[threadIdx.x];
    __syncthreads();

    const int warp = threadIdx.x >> 5;
    const int lane = threadIdx.x & 31;
    const int mbase = (blockIdx.x * 8 + warp) * ROWS_PER_WARP;

    for (int g = 0; g < ROWS_PER_WARP; g++) {
        const int m = mbase + g;

        const uint32_t* gb = g_ballot + (size_t)m * 16;
        uint32_t w = (lane < 16) ? gb[lane] : 0u;

        float acc[Odim];
        #pragma unroll
        for (int o = 0; o < Odim; o++) acc[o] = 0.f;

        #pragma unroll
        for (int j = 0; j < 16; j++) {           // h = j*32 + lane (ascending)
            const uint32_t wj = __shfl_sync(0xffffffffu, w, j);
            const float s = ((wj >> lane) & 1u) ? 1.f : 0.f;
            const int hh = j * 32 + lane;
            #pragma unroll
            for (int o = 0; o < Odim; o++)
                acc[o] = fmaf(s, WrS[o * Hdim + hh], acc[o]);
        }

        #pragma unroll
        for (int o = 0; o < Odim; o++)
            #pragma unroll
            for (int d = 16; d; d >>= 1)
                acc[o] += __shfl_xor_sync(0xffffffffu, acc[o], d);

        if (lane == 0) {
            #pragma unroll
            for (int o = 0; o < Odim; o++)
                Out[(size_t)m * Odim + o] = acc[o] + brS[o];
        }
    }
}

// ---------------------------------------------------------------------------
// Launch
// ---------------------------------------------------------------------------
extern "C" void kernel_launch(void* const* d_in, const int* in_sizes, int n_in,
                              void* d_out, int out_size)
{
    const float* input_data = (const float*)d_in[0];
    const float* W1     = (const float*)d_in[1];
    const float* b1     = (const float*)d_in[2];
    const float* W2     = (const float*)d_in[3];
    const float* b2     = (const float*)d_in[4];
    const float* tau_m  = (const float*)d_in[5];
    const float* tau_n1 = (const float*)d_in[6];
    const float* tau_n2 = (const float*)d_in[7];
    const float* Wr     = (const float*)d_in[8];
    const float* br     = (const float*)d_in[9];
    const float* mem0   = (const float*)d_in[10];
    const float* spike0 = (const float*)d_in[11];
    float* out = (float*)d_out;

    (void)in_sizes; (void)n_in; (void)out_size;

    float *w1t, *w2t;
    cudaGetSymbolAddress((void**)&w1t, g_w1t);
    cudaGetSymbolAddress((void**)&w2t, g_w2t);

    // Pre-transpose only the weights (1 MB each; X stays row-major)
    transpose_w_kernel<<<dim3(Hdim / 32, Kdim / 32, 2), 256>>>(W1, W2);

    cudaFuncSetAttribute(gemm_fused_kernel,
                         cudaFuncAttributeMaxDynamicSharedMemorySize, SMEM_BYTES);

    gemm_fused_kernel<<<dim3(Hdim / 128, Mdim / 128), 256, SMEM_BYTES>>>(
        input_data, w1t, b1, w2t, b2);

    scan_kernel<<<(Bdim * Hdim) / 256, 256>>>(tau_m, tau_n1, tau_n2, mem0, spike0);

    readout_kernel<<<Mdim / (8 * ROWS_PER_WARP), 256>>>(Wr, br, out);
}

// round 15
// speedup vs baseline: 1.0287x; 1.0185x over previous
#include <cuda_runtime.h>
#include <cuda_bf16.h>
#include <cstdint>

// Problem shape (fixed for this bench)
#define Bdim 128
#define Tdim 784
#define Kdim 512   // K of branch GEMMs
#define Hdim 512   // N of branch GEMMs
#define Odim 10
#define Mdim (Bdim * Tdim)   // 100352

// ---------------------------------------------------------------------------
// Scratch (device globals: allocation inside kernel_launch is forbidden)
// ---------------------------------------------------------------------------
__device__ float    g_d1[(size_t)Mdim * Hdim];
__device__ float    g_d2[(size_t)Mdim * Hdim];
__device__ uint32_t g_ballot[(size_t)Mdim * 16];   // 512 spikes -> 16 words per (b,t)
__device__ float    g_w1t[Kdim * Hdim];            // W1 transposed [K][N]
__device__ float    g_w2t[Kdim * Hdim];            // W2 transposed [K][N]

__device__ __forceinline__ uint32_t smem_u32(const void* p) {
    uint32_t a;
    asm("{ .reg .u64 t; cvta.to.shared.u64 t, %1; cvt.u32.u64 %0, t; }"
        : "=r"(a) : "l"(p));
    return a;
}

// ---------------------------------------------------------------------------
// Transpose: dst[C][R] = src[R][C]  (used only for W1/W2 — 1 MB each)
// ---------------------------------------------------------------------------
__global__ void __launch_bounds__(256) transpose_w_kernel(
    const float* __restrict__ W1, const float* __restrict__ W2)
{
    __shared__ float tile[32][33];
    const float* src = blockIdx.z ? W2 : W1;
    float* dst = blockIdx.z ? g_w2t : g_w1t;
    const int r0 = blockIdx.x * 32;
    const int c0 = blockIdx.y * 32;
    const int tx = threadIdx.x & 31;
    const int ty = threadIdx.x >> 5;   // 0..7
    #pragma unroll
    for (int j = 0; j < 4; j++)
        tile[ty + j * 8][tx] = src[(size_t)(r0 + ty + j * 8) * Kdim + c0 + tx];
    __syncthreads();
    #pragma unroll
    for (int j = 0; j < 4; j++)
        dst[(size_t)(c0 + ty + j * 8) * Hdim + r0 + tx] = tile[tx][ty + j * 8];
}

// ---------------------------------------------------------------------------
// Fused dual-branch GEMM: d1 = X@W1^T + b1 AND d2 = X@W2^T + b2 in one CTA.
//   Bit-exact fp32: ascending-k scalar IEEE FMA chain per output.
//   X staged in registers (row-major LDG) + transposing STS; W1/W2 via
//   cp.async from pre-transposed copies. CTA tile 128m x 128n x 2 branches.
// ---------------------------------------------------------------------------
#define BK 16
#define LDSX 132                      // floats per k-row (128 data + 4 pad)
#define XBUF (BK * LDSX)              // 2112 floats per stage per matrix
#define NCHUNK (Kdim / BK)            // 32
#define SMEM_BYTES (6 * XBUF * 4)     // 2 stages x (X + W1 + W2) = 50688 B

#define CP16(s, g) \
    asm volatile("cp.async.cg.shared.global [%0], [%1], 16;" :: "r"(s), "l"(g) : "memory")

__global__ void __launch_bounds__(256, 1) gemm_fused_kernel(
    const float* __restrict__ X,
    const float* __restrict__ W1t, const float* __restrict__ b1,
    const float* __restrict__ W2t, const float* __restrict__ b2)
{
    extern __shared__ float sm[];
    float* Xs  = sm;                  // [2][BK][LDSX]  Xs[k][m]
    float* W1s = sm + 2 * XBUF;       // [2][BK][LDSX]  W1s[k][n]
    float* W2s = sm + 4 * XBUF;       // [2][BK][LDSX]  W2s[k][n]
    const uint32_t smbase = smem_u32(sm);

    const int tid  = threadIdx.x;
    const int lane = tid & 31;
    const int wid  = tid >> 5;
    const int mloc = (wid & 3) * 32 + (lane >> 3) * 8;   // thread row base
    const int nloc = (wid >> 2) * 64 + (lane & 7) * 8;   // thread col base

    const int n0 = blockIdx.x * 128;
    const int m0 = blockIdx.y * 128;

    // X loader mapping (row-major, coalesced): rows tid>>2 (+64), cols (tid&3)*4
    const int lrow = tid >> 2;
    const int lcol = (tid & 3) * 4;
    const float* xg = X + (size_t)(m0 + lrow) * Kdim + lcol;

    // W cp.async mapping: k-row = tid>>4 (0..15), float cols (tid&15)*4 and +64
    const int crow = tid >> 4;
    const int ccol = (tid & 15) * 4;
    const uint32_t cp_soff = (uint32_t)(crow * LDSX + ccol) * 4;
    const float* w1gp = W1t + (size_t)crow * Hdim + n0 + ccol;
    const float* w2gp = W2t + (size_t)crow * Hdim + n0 + ccol;

#define LDG_X(c) do {                                                        \
        xr[0] = *(const float4*)(xg + (c) * BK);                             \
        xr[1] = *(const float4*)(xg + (size_t)64 * Kdim + (c) * BK);         \
    } while (0)

#define STS_X(p) do {                                                        \
        _Pragma("unroll")                                                    \
        for (int _r = 0; _r < 2; _r++) {                                     \
            const float _xv[4] = {xr[_r].x, xr[_r].y, xr[_r].z, xr[_r].w};   \
            _Pragma("unroll")                                                \
            for (int _u = 0; _u < 4; _u++)                                   \
                Xs[(p) * XBUF + (lcol + _u) * LDSX + lrow + _r * 64] = _xv[_u]; \
        }                                                                    \
    } while (0)

#define CP_W(c, p) do {                                                      \
        const size_t _kw = (size_t)(c) * BK * Hdim;                          \
        const uint32_t _s1 = smbase + ((2 + (p)) * XBUF) * 4 + cp_soff;      \
        const uint32_t _s2 = smbase + ((4 + (p)) * XBUF) * 4 + cp_soff;      \
        CP16(_s1,       w1gp + _kw);                                         \
        CP16(_s1 + 256, w1gp + _kw + 64);                                    \
        CP16(_s2,       w2gp + _kw);                                         \
        CP16(_s2 + 256, w2gp + _kw + 64);                                    \
        asm volatile("cp.async.commit_group;" ::: "memory");                 \
    } while (0)

#define LDFRAG(buf, kk) do {                                                 \
        const float* _xr = xb  + (kk) * LDSX + mloc;                         \
        const float* _w1 = w1b + (kk) * LDSX + nloc;                         \
        const float* _w2 = w2b + (kk) * LDSX + nloc;                         \
        *(float4*)&fa[buf][0] = *(const float4*)_xr;                         \
        *(float4*)&fa[buf][4] = *(const float4*)(_xr + 4);                   \
        *(float4*)&f1[buf][0] = *(const float4*)_w1;                         \
        *(float4*)&f1[buf][4] = *(const float4*)(_w1 + 4);                   \
        *(float4*)&f2[buf][0] = *(const float4*)_w2;                         \
        *(float4*)&f2[buf][4] = *(const float4*)(_w2 + 4);                   \
    } while (0)

    float acc1[8][8], acc2[8][8];
    #pragma unroll
    for (int i = 0; i < 8; i++)
        #pragma unroll
        for (int j = 0; j < 8; j++) { acc1[i][j] = 0.f; acc2[i][j] = 0.f; }

    float4 xr[2];

    // Prologue: chunk 0 fully staged; X of chunk 1 in registers.
    LDG_X(0);
    STS_X(0);
    CP_W(0, 0);
    LDG_X(1);

    for (int c = 0; c < NCHUNK; ++c) {
        const int p = c & 1;
        asm volatile("cp.async.wait_group 0;" ::: "memory");  // chunk c's W in
        __syncthreads();   // stage p complete (X STS'd last iter, W arrived)

        if (c + 1 < NCHUNK) {
            STS_X(p ^ 1);          // X chunk c+1 from registers
            CP_W(c + 1, p ^ 1);    // W chunk c+1 (lands during this compute)
        }
        if (c + 2 < NCHUNK) LDG_X(c + 2);   // X chunk c+2 into registers

        const float* xb  = Xs  + p * XBUF;
        const float* w1b = W1s + p * XBUF;
        const float* w2b = W2s + p * XBUF;

        float fa[2][8], f1[2][8], f2[2][8];
        LDFRAG(0, 0);
        #pragma unroll
        for (int kk = 0; kk < BK; kk++) {
            const int cur = kk & 1;
            if (kk < BK - 1) LDFRAG(cur ^ 1, kk + 1);
            #pragma unroll
            for (int i = 0; i < 8; i++)
                #pragma unroll
                for (int j = 0; j < 8; j++) {
                    acc1[i][j] = fmaf(fa[cur][i], f1[cur][j], acc1[i][j]);
                    acc2[i][j] = fmaf(fa[cur][i], f2[cur][j], acc2[i][j]);
                }
        }
    }

    // Epilogue: add bias, store both branches
    {
        const int nb = n0 + nloc;
        float bs1[8], bs2[8];
        #pragma unroll
        for (int j = 0; j < 8; j++) { bs1[j] = b1[nb + j]; bs2[j] = b2[nb + j]; }

        #pragma unroll
        for (int i = 0; i < 8; i++) {
            const int m = m0 + mloc + i;
            float* d1p = g_d1 + (size_t)m * Hdim + nb;
            float* d2p = g_d2 + (size_t)m * Hdim + nb;
            *(float4*)d1p = make_float4(acc1[i][0] + bs1[0], acc1[i][1] + bs1[1],
                                        acc1[i][2] + bs1[2], acc1[i][3] + bs1[3]);
            *(float4*)(d1p + 4) = make_float4(acc1[i][4] + bs1[4], acc1[i][5] + bs1[5],
                                              acc1[i][6] + bs1[6], acc1[i][7] + bs1[7]);
            *(float4*)d2p = make_float4(acc2[i][0] + bs2[0], acc2[i][1] + bs2[1],
                                        acc2[i][2] + bs2[2], acc2[i][3] + bs2[3]);
            *(float4*)(d2p + 4) = make_float4(acc2[i][4] + bs2[4], acc2[i][5] + bs2[5],
                                              acc2[i][6] + bs2[6], acc2[i][7] + bs2[7]);
        }
    }
}

// ---------------------------------------------------------------------------
// Kernel B: sequential LIF scan, software-pipelined in batches of 8 timesteps.
// ---------------------------------------------------------------------------
__device__ __forceinline__ float sigmoidf(float x) { return 1.f / (1.f + expf(-x)); }

#define SB 8                          // timestep batch (784 = 8*98)

__global__ void __launch_bounds__(256) scan_kernel(
    const float* __restrict__ tau_m,
    const float* __restrict__ tau_n1,
    const float* __restrict__ tau_n2,
    const float* __restrict__ mem0,
    const float* __restrict__ spike0)
{
    const int tid = blockIdx.x * blockDim.x + threadIdx.x;
    const int b = tid / Hdim;
    const int h = tid - b * Hdim;
    const int lane = threadIdx.x & 31;

    const float alpha = sigmoidf(tau_m[h]);
    const float beta1 = sigmoidf(tau_n1[h]);
    const float beta2 = sigmoidf(tau_n2[h]);
    const float om_a = 1.f - alpha, om_b1 = 1.f - beta1, om_b2 = 1.f - beta2;

    float mem = mem0[tid];
    float spk = spike0[tid];
    float d1 = 0.f, d2 = 0.f;

    size_t base = ((size_t)b * Tdim) * Hdim + h;
    size_t bidx = ((size_t)b * Tdim) * 16 + (h >> 5);
    const float* __restrict__ D1 = g_d1;
    const float* __restrict__ D2 = g_d2;

    float pd1[SB], pd2[SB];
    #pragma unroll
    for (int j = 0; j < SB; j++) {
        pd1[j] = __ldcs(D1 + base + (size_t)j * Hdim);
        pd2[j] = __ldcs(D2 + base + (size_t)j * Hdim);
    }

    for (int tb = 0; tb < Tdim / SB; tb++) {
        float nd1[SB], nd2[SB];
        if (tb < Tdim / SB - 1) {
            #pragma unroll
            for (int j = 0; j < SB; j++) {
                nd1[j] = __ldcs(D1 + base + (size_t)(SB + j) * Hdim);
                nd2[j] = __ldcs(D2 + base + (size_t)(SB + j) * Hdim);
            }
        }
        #pragma unroll
        for (int j = 0; j < SB; j++) {
            float d1t = pd1[j];
            float d2t = pd2[j];
            d1 = beta1 * d1 + om_b1 * d1t;
            d2 = beta2 * d2 + om_b2 * d2t;
            mem = mem * alpha + om_a * (d1 + d2) - spk;   // V_TH = 1
            spk = (mem > 1.f) ? 1.f : 0.f;
            unsigned bal = __ballot_sync(0xffffffffu, mem > 1.f);
            if (lane == 0) g_ballot[bidx + (size_t)j * 16] = bal;
        }
        #pragma unroll
        for (int j = 0; j < SB; j++) { pd1[j] = nd1[j]; pd2[j] = nd2[j]; }
        base += (size_t)SB * Hdim;
        bidx += (size_t)SB * 16;
    }
}

// ---------------------------------------------------------------------------
// Kernel C: readout from spike ballots, Wr loads hoisted over rows.
//   Warp owns 8 rows; their 128 ballot words are staged as one uint4/lane
//   (lane l holds row l>>2, words (l&3)*4+i). Per j, each lane loads its 10
//   Wr values ONCE and reuses them for all 8 rows -> 8x less LDS traffic.
//   Per-lane h-order (h=j*32+lane, ascending j) and the shuffle-xor tree are
//   unchanged -> bit-identical to the previous readout.
// ---------------------------------------------------------------------------
#define ROWS_PER_WARP 8

__global__ void __launch_bounds__(256) readout_kernel(
    const float* __restrict__ Wr,
    const float* __restrict__ br,
    float* __restrict__ Out)
{
    __shared__ float WrS[Odim * Hdim];   // 20 KB
    __shared__ float brS[Odim];
    for (int i = threadIdx.x; i < Odim * Hdim; i += blockDim.x) WrS[i] = Wr[i];
    if (threadIdx.x < Odim) brS[threadIdx.x] = br[threadIdx.x];
    __syncthreads();

    const int warp = threadIdx.x >> 5;
    const int lane = threadIdx.x & 31;
    const int mbase = (blockIdx.x * 8 + warp) * ROWS_PER_WARP;

    // Stage 8 rows x 16 ballot words = 512B per warp, one uint4 per lane.
    const uint4 wv = *(const uint4*)(g_ballot + (size_t)mbase * 16 + lane * 4);
    uint32_t w[4] = {wv.x, wv.y, wv.z, wv.w};

    float acc[ROWS_PER_WARP][Odim];
    #pragma unroll
    for (int g = 0; g < ROWS_PER_WARP; g++)
        #pragma unroll
        for (int o = 0; o < Odim; o++) acc[g][o] = 0.f;

    #pragma unroll
    for (int j = 0; j < 16; j++) {               // h = j*32 + lane (ascending)
        const int hh = j * 32 + lane;
        float wr[Odim];
        #pragma unroll
        for (int o = 0; o < Odim; o++) wr[o] = WrS[o * Hdim + hh];

        #pragma unroll
        for (int g = 0; g < ROWS_PER_WARP; g++) {
            // word j of row g lives in lane g*4 + (j>>2), register j&3
            const uint32_t wjg = __shfl_sync(0xffffffffu, w[j & 3],
                                             g * 4 + (j >> 2));
            const float s = ((wjg >> lane) & 1u) ? 1.f : 0.f;
            #pragma unroll
            for (int o = 0; o < Odim; o++)
                acc[g][o] = fmaf(s, wr[o], acc[g][o]);
        }
    }

    #pragma unroll
    for (int g = 0; g < ROWS_PER_WARP; g++) {
        #pragma unroll
        for (int o = 0; o < Odim; o++)
            #pragma unroll
            for (int d = 16; d; d >>= 1)
                acc[g][o] += __shfl_xor_sync(0xffffffffu, acc[g][o], d);
        if (lane == 0) {
            #pragma unroll
            for (int o = 0; o < Odim; o++)
                Out[(size_t)(mbase + g) * Odim + o] = acc[g][o] + brS[o];
        }
    }
}

// ---------------------------------------------------------------------------
// Launch
// ---------------------------------------------------------------------------
extern "C" void kernel_launch(void* const* d_in, const int* in_sizes, int n_in,
                              void* d_out, int out_size)
{
    const float* input_data = (const float*)d_in[0];
    const float* W1     = (const float*)d_in[1];
    const float* b1     = (const float*)d_in[2];
    const float* W2     = (const float*)d_in[3];
    const float* b2     = (const float*)d_in[4];
    const float* tau_m  = (const float*)d_in[5];
    const float* tau_n1 = (const float*)d_in[6];
    const float* tau_n2 = (const float*)d_in[7];
    const float* Wr     = (const float*)d_in[8];
    const float* br     = (const float*)d_in[9];
    const float* mem0   = (const float*)d_in[10];
    const float* spike0 = (const float*)d_in[11];
    float* out = (float*)d_out;

    (void)in_sizes; (void)n_in; (void)out_size;

    float *w1t, *w2t;
    cudaGetSymbolAddress((void**)&w1t, g_w1t);
    cudaGetSymbolAddress((void**)&w2t, g_w2t);

    // Pre-transpose only the weights (1 MB each; X stays row-major)
    transpose_w_kernel<<<dim3(Hdim / 32, Kdim / 32, 2), 256>>>(W1, W2);

    cudaFuncSetAttribute(gemm_fused_kernel,
                         cudaFuncAttributeMaxDynamicSharedMemorySize, SMEM_BYTES);

    gemm_fused_kernel<<<dim3(Hdim / 128, Mdim / 128), 256, SMEM_BYTES>>>(
        input_data, w1t, b1, w2t, b2);

    scan_kernel<<<(Bdim * Hdim) / 256, 256>>>(tau_m, tau_n1, tau_n2, mem0, spike0);

    readout_kernel<<<Mdim / (8 * ROWS_PER_WARP), 256>>>(Wr, br, out);
}

// round 16
// speedup vs baseline: 1.0386x; 1.0096x over previous
#include <cuda_runtime.h>
#include <cuda_bf16.h>
#include <cstdint>

// Problem shape (fixed for this bench)
#define Bdim 128
#define Tdim 784
#define Kdim 512   // K of branch GEMMs
#define Hdim 512   // N of branch GEMMs
#define Odim 10
#define Mdim (Bdim * Tdim)   // 100352

// ---------------------------------------------------------------------------
// Scratch (device globals: allocation inside kernel_launch is forbidden)
// ---------------------------------------------------------------------------
__device__ float    g_d1[(size_t)Mdim * Hdim];
__device__ float    g_d2[(size_t)Mdim * Hdim];
__device__ uint32_t g_ballot[(size_t)Mdim * 16];   // 512 spikes -> 16 words per (b,t)
__device__ float    g_w1t[Kdim * Hdim];            // W1 transposed [K][N]
__device__ float    g_w2t[Kdim * Hdim];            // W2 transposed [K][N]

__device__ __forceinline__ uint32_t smem_u32(const void* p) {
    uint32_t a;
    asm("{ .reg .u64 t; cvta.to.shared.u64 t, %1; cvt.u32.u64 %0, t; }"
        : "=r"(a) : "l"(p));
    return a;
}

// ---------------------------------------------------------------------------
// Transpose: dst[C][R] = src[R][C]  (used only for W1/W2 — 1 MB each)
// ---------------------------------------------------------------------------
__global__ void __launch_bounds__(256) transpose_w_kernel(
    const float* __restrict__ W1, const float* __restrict__ W2)
{
    __shared__ float tile[32][33];
    const float* src = blockIdx.z ? W2 : W1;
    float* dst = blockIdx.z ? g_w2t : g_w1t;
    const int r0 = blockIdx.x * 32;
    const int c0 = blockIdx.y * 32;
    const int tx = threadIdx.x & 31;
    const int ty = threadIdx.x >> 5;   // 0..7
    #pragma unroll
    for (int j = 0; j < 4; j++)
        tile[ty + j * 8][tx] = src[(size_t)(r0 + ty + j * 8) * Kdim + c0 + tx];
    __syncthreads();
    #pragma unroll
    for (int j = 0; j < 4; j++)
        dst[(size_t)(c0 + ty + j * 8) * Hdim + r0 + tx] = tile[tx][ty + j * 8];
}

// ---------------------------------------------------------------------------
// Fused dual-branch GEMM: d1 = X@W1^T + b1 AND d2 = X@W2^T + b2 in one CTA.
//   Bit-exact fp32: ascending-k scalar IEEE FMA chain per output.
//   X staged in registers (row-major LDG) + transposing STS; W1/W2 via
//   cp.async from pre-transposed copies. CTA tile 128m x 128n x 2 branches.
// ---------------------------------------------------------------------------
#define BK 16
#define LDSX 132                      // floats per k-row (128 data + 4 pad)
#define XBUF (BK * LDSX)              // 2112 floats per stage per matrix
#define NCHUNK (Kdim / BK)            // 32
#define SMEM_BYTES (6 * XBUF * 4)     // 2 stages x (X + W1 + W2) = 50688 B

#define CP16(s, g) \
    asm volatile("cp.async.cg.shared.global [%0], [%1], 16;" :: "r"(s), "l"(g) : "memory")

__global__ void __launch_bounds__(256, 1) gemm_fused_kernel(
    const float* __restrict__ X,
    const float* __restrict__ W1t, const float* __restrict__ b1,
    const float* __restrict__ W2t, const float* __restrict__ b2)
{
    extern __shared__ float sm[];
    float* Xs  = sm;                  // [2][BK][LDSX]  Xs[k][m]
    float* W1s = sm + 2 * XBUF;       // [2][BK][LDSX]  W1s[k][n]
    float* W2s = sm + 4 * XBUF;       // [2][BK][LDSX]  W2s[k][n]
    const uint32_t smbase = smem_u32(sm);

    const int tid  = threadIdx.x;
    const int lane = tid & 31;
    const int wid  = tid >> 5;
    const int mloc = (wid & 3) * 32 + (lane >> 3) * 8;   // thread row base
    const int nloc = (wid >> 2) * 64 + (lane & 7) * 8;   // thread col base

    const int n0 = blockIdx.x * 128;
    const int m0 = blockIdx.y * 128;

    // X loader mapping (row-major, coalesced): rows tid>>2 (+64), cols (tid&3)*4
    const int lrow = tid >> 2;
    const int lcol = (tid & 3) * 4;
    const float* xg = X + (size_t)(m0 + lrow) * Kdim + lcol;

    // W cp.async mapping: k-row = tid>>4 (0..15), float cols (tid&15)*4 and +64
    const int crow = tid >> 4;
    const int ccol = (tid & 15) * 4;
    const uint32_t cp_soff = (uint32_t)(crow * LDSX + ccol) * 4;
    const float* w1gp = W1t + (size_t)crow * Hdim + n0 + ccol;
    const float* w2gp = W2t + (size_t)crow * Hdim + n0 + ccol;

#define LDG_X(c) do {                                                        \
        xr[0] = *(const float4*)(xg + (c) * BK);                             \
        xr[1] = *(const float4*)(xg + (size_t)64 * Kdim + (c) * BK);         \
    } while (0)

#define STS_X(p) do {                                                        \
        _Pragma("unroll")                                                    \
        for (int _r = 0; _r < 2; _r++) {                                     \
            const float _xv[4] = {xr[_r].x, xr[_r].y, xr[_r].z, xr[_r].w};   \
            _Pragma("unroll")                                                \
            for (int _u = 0; _u < 4; _u++)                                   \
                Xs[(p) * XBUF + (lcol + _u) * LDSX + lrow + _r * 64] = _xv[_u]; \
        }                                                                    \
    } while (0)

#define CP_W(c, p) do {                                                      \
        const size_t _kw = (size_t)(c) * BK * Hdim;                          \
        const uint32_t _s1 = smbase + ((2 + (p)) * XBUF) * 4 + cp_soff;      \
        const uint32_t _s2 = smbase + ((4 + (p)) * XBUF) * 4 + cp_soff;      \
        CP16(_s1,       w1gp + _kw);                                         \
        CP16(_s1 + 256, w1gp + _kw + 64);                                    \
        CP16(_s2,       w2gp + _kw);                                         \
        CP16(_s2 + 256, w2gp + _kw + 64);                                    \
        asm volatile("cp.async.commit_group;" ::: "memory");                 \
    } while (0)

#define LDFRAG(buf, kk) do {                                                 \
        const float* _xr = xb  + (kk) * LDSX + mloc;                         \
        const float* _w1 = w1b + (kk) * LDSX + nloc;                         \
        const float* _w2 = w2b + (kk) * LDSX + nloc;                         \
        *(float4*)&fa[buf][0] = *(const float4*)_xr;                         \
        *(float4*)&fa[buf][4] = *(const float4*)(_xr + 4);                   \
        *(float4*)&f1[buf][0] = *(const float4*)_w1;                         \
        *(float4*)&f1[buf][4] = *(const float4*)(_w1 + 4);                   \
        *(float4*)&f2[buf][0] = *(const float4*)_w2;                         \
        *(float4*)&f2[buf][4] = *(const float4*)(_w2 + 4);                   \
    } while (0)

    float acc1[8][8], acc2[8][8];
    #pragma unroll
    for (int i = 0; i < 8; i++)
        #pragma unroll
        for (int j = 0; j < 8; j++) { acc1[i][j] = 0.f; acc2[i][j] = 0.f; }

    float4 xr[2];

    // Prologue: chunk 0 fully staged; X of chunk 1 in registers.
    LDG_X(0);
    STS_X(0);
    CP_W(0, 0);
    LDG_X(1);

    for (int c = 0; c < NCHUNK; ++c) {
        const int p = c & 1;
        asm volatile("cp.async.wait_group 0;" ::: "memory");  // chunk c's W in
        __syncthreads();   // stage p complete (X STS'd last iter, W arrived)

        if (c + 1 < NCHUNK) {
            STS_X(p ^ 1);          // X chunk c+1 from registers
            CP_W(c + 1, p ^ 1);    // W chunk c+1 (lands during this compute)
        }
        if (c + 2 < NCHUNK) LDG_X(c + 2);   // X chunk c+2 into registers

        const float* xb  = Xs  + p * XBUF;
        const float* w1b = W1s + p * XBUF;
        const float* w2b = W2s + p * XBUF;

        float fa[2][8], f1[2][8], f2[2][8];
        LDFRAG(0, 0);
        #pragma unroll
        for (int kk = 0; kk < BK; kk++) {
            const int cur = kk & 1;
            if (kk < BK - 1) LDFRAG(cur ^ 1, kk + 1);
            #pragma unroll
            for (int i = 0; i < 8; i++)
                #pragma unroll
                for (int j = 0; j < 8; j++) {
                    acc1[i][j] = fmaf(fa[cur][i], f1[cur][j], acc1[i][j]);
                    acc2[i][j] = fmaf(fa[cur][i], f2[cur][j], acc2[i][j]);
                }
        }
    }

    // Epilogue: add bias, store both branches
    {
        const int nb = n0 + nloc;
        float bs1[8], bs2[8];
        #pragma unroll
        for (int j = 0; j < 8; j++) { bs1[j] = b1[nb + j]; bs2[j] = b2[nb + j]; }

        #pragma unroll
        for (int i = 0; i < 8; i++) {
            const int m = m0 + mloc + i;
            float* d1p = g_d1 + (size_t)m * Hdim + nb;
            float* d2p = g_d2 + (size_t)m * Hdim + nb;
            *(float4*)d1p = make_float4(acc1[i][0] + bs1[0], acc1[i][1] + bs1[1],
                                        acc1[i][2] + bs1[2], acc1[i][3] + bs1[3]);
            *(float4*)(d1p + 4) = make_float4(acc1[i][4] + bs1[4], acc1[i][5] + bs1[5],
                                              acc1[i][6] + bs1[6], acc1[i][7] + bs1[7]);
            *(float4*)d2p = make_float4(acc2[i][0] + bs2[0], acc2[i][1] + bs2[1],
                                        acc2[i][2] + bs2[2], acc2[i][3] + bs2[3]);
            *(float4*)(d2p + 4) = make_float4(acc2[i][4] + bs2[4], acc2[i][5] + bs2[5],
                                              acc2[i][6] + bs2[6], acc2[i][7] + bs2[7]);
        }
    }
}

// ---------------------------------------------------------------------------
// Kernel B: sequential LIF scan, software-pipelined in batches of 16 timesteps
// (784 = 49*16). Loads for batch tb+1 are in flight while batch tb computes,
// so ~32 outstanding loads/thread cover DRAM latency across the ballot
// scheduling barriers. Recurrence statements textually identical ->
// bit-identical spikes.
// ---------------------------------------------------------------------------
__device__ __forceinline__ float sigmoidf(float x) { return 1.f / (1.f + expf(-x)); }

#define SB 16                         // timestep batch (784 = 16*49)

__global__ void __launch_bounds__(256) scan_kernel(
    const float* __restrict__ tau_m,
    const float* __restrict__ tau_n1,
    const float* __restrict__ tau_n2,
    const float* __restrict__ mem0,
    const float* __restrict__ spike0)
{
    const int tid = blockIdx.x * blockDim.x + threadIdx.x;
    const int b = tid / Hdim;
    const int h = tid - b * Hdim;
    const int lane = threadIdx.x & 31;

    const float alpha = sigmoidf(tau_m[h]);
    const float beta1 = sigmoidf(tau_n1[h]);
    const float beta2 = sigmoidf(tau_n2[h]);
    const float om_a = 1.f - alpha, om_b1 = 1.f - beta1, om_b2 = 1.f - beta2;

    float mem = mem0[tid];
    float spk = spike0[tid];
    float d1 = 0.f, d2 = 0.f;

    size_t base = ((size_t)b * Tdim) * Hdim + h;
    size_t bidx = ((size_t)b * Tdim) * 16 + (h >> 5);
    const float* __restrict__ D1 = g_d1;
    const float* __restrict__ D2 = g_d2;

    float pd1[SB], pd2[SB];
    #pragma unroll
    for (int j = 0; j < SB; j++) {
        pd1[j] = __ldcs(D1 + base + (size_t)j * Hdim);
        pd2[j] = __ldcs(D2 + base + (size_t)j * Hdim);
    }

    for (int tb = 0; tb < Tdim / SB; tb++) {
        float nd1[SB], nd2[SB];
        if (tb < Tdim / SB - 1) {
            #pragma unroll
            for (int j = 0; j < SB; j++) {
                nd1[j] = __ldcs(D1 + base + (size_t)(SB + j) * Hdim);
                nd2[j] = __ldcs(D2 + base + (size_t)(SB + j) * Hdim);
            }
        }
        #pragma unroll
        for (int j = 0; j < SB; j++) {
            float d1t = pd1[j];
            float d2t = pd2[j];
            d1 = beta1 * d1 + om_b1 * d1t;
            d2 = beta2 * d2 + om_b2 * d2t;
            mem = mem * alpha + om_a * (d1 + d2) - spk;   // V_TH = 1
            spk = (mem > 1.f) ? 1.f : 0.f;
            unsigned bal = __ballot_sync(0xffffffffu, mem > 1.f);
            if (lane == 0) g_ballot[bidx + (size_t)j * 16] = bal;
        }
        #pragma unroll
        for (int j = 0; j < SB; j++) { pd1[j] = nd1[j]; pd2[j] = nd2[j]; }
        base += (size_t)SB * Hdim;
        bidx += (size_t)SB * 16;
    }
}

// ---------------------------------------------------------------------------
// Kernel C: readout from spike ballots, Wr loads hoisted over rows.
// ---------------------------------------------------------------------------
#define ROWS_PER_WARP 8

__global__ void __launch_bounds__(256) readout_kernel(
    const float* __restrict__ Wr,
    const float* __restrict__ br,
    float* __restrict__ Out)
{
    __shared__ float WrS[Odim * Hdim];   // 20 KB
    __shared__ float brS[Odim];
    for (int i = threadIdx.x; i < Odim * Hdim; i += blockDim.x) WrS[i] = Wr[i];
    if (threadIdx.x < Odim) brS[threadIdx.x] = br[threadIdx.x];
    __syncthreads();

    const int warp = threadIdx.x >> 5;
    const int lane = threadIdx.x & 31;
    const int mbase = (blockIdx.x * 8 + warp) * ROWS_PER_WARP;

    // Stage 8 rows x 16 ballot words = 512B per warp, one uint4 per lane.
    const uint4 wv = *(const uint4*)(g_ballot + (size_t)mbase * 16 + lane * 4);
    uint32_t w[4] = {wv.x, wv.y, wv.z, wv.w};

    float acc[ROWS_PER_WARP][Odim];
    #pragma unroll
    for (int g = 0; g < ROWS_PER_WARP; g++)
        #pragma unroll
        for (int o = 0; o < Odim; o++) acc[g][o] = 0.f;

    #pragma unroll
    for (int j = 0; j < 16; j++) {               // h = j*32 + lane (ascending)
        const int hh = j * 32 + lane;
        float wr[Odim];
        #pragma unroll
        for (int o = 0; o < Odim; o++) wr[o] = WrS[o * Hdim + hh];

        #pragma unroll
        for (int g = 0; g < ROWS_PER_WARP; g++) {
            // word j of row g lives in lane g*4 + (j>>2), register j&3
            const uint32_t wjg = __shfl_sync(0xffffffffu, w[j & 3],
                                             g * 4 + (j >> 2));
            const float s = ((wjg >> lane) & 1u) ? 1.f : 0.f;
            #pragma unroll
            for (int o = 0; o < Odim; o++)
                acc[g][o] = fmaf(s, wr[o], acc[g][o]);
        }
    }

    #pragma unroll
    for (int g = 0; g < ROWS_PER_WARP; g++) {
        #pragma unroll
        for (int o = 0; o < Odim; o++)
            #pragma unroll
            for (int d = 16; d; d >>= 1)
                acc[g][o] += __shfl_xor_sync(0xffffffffu, acc[g][o], d);
        if (lane == 0) {
            #pragma unroll
            for (int o = 0; o < Odim; o++)
                Out[(size_t)(mbase + g) * Odim + o] = acc[g][o] + brS[o];
        }
    }
}

// ---------------------------------------------------------------------------
// Launch
// ---------------------------------------------------------------------------
extern "C" void kernel_launch(void* const* d_in, const int* in_sizes, int n_in,
                              void* d_out, int out_size)
{
    const float* input_data = (const float*)d_in[0];
    const float* W1     = (const float*)d_in[1];
    const float* b1     = (const float*)d_in[2];
    const float* W2     = (const float*)d_in[3];
    const float* b2     = (const float*)d_in[4];
    const float* tau_m  = (const float*)d_in[5];
    const float* tau_n1 = (const float*)d_in[6];
    const float* tau_n2 = (const float*)d_in[7];
    const float* Wr     = (const float*)d_in[8];
    const float* br     = (const float*)d_in[9];
    const float* mem0   = (const float*)d_in[10];
    const float* spike0 = (const float*)d_in[11];
    float* out = (float*)d_out;

    (void)in_sizes; (void)n_in; (void)out_size;

    float *w1t, *w2t;
    cudaGetSymbolAddress((void**)&w1t, g_w1t);
    cudaGetSymbolAddress((void**)&w2t, g_w2t);

    // Pre-transpose only the weights (1 MB each; X stays row-major)
    transpose_w_kernel<<<dim3(Hdim / 32, Kdim / 32, 2), 256>>>(W1, W2);

    cudaFuncSetAttribute(gemm_fused_kernel,
                         cudaFuncAttributeMaxDynamicSharedMemorySize, SMEM_BYTES);

    gemm_fused_kernel<<<dim3(Hdim / 128, Mdim / 128), 256, SMEM_BYTES>>>(
        input_data, w1t, b1, w2t, b2);

    scan_kernel<<<(Bdim * Hdim) / 256, 256>>>(tau_m, tau_n1, tau_n2, mem0, spike0);

    readout_kernel<<<Mdim / (8 * ROWS_PER_WARP), 256>>>(Wr, br, out);
}

// round 17
// speedup vs baseline: 1.0421x; 1.0034x over previous
#include <cuda_runtime.h>
#include <cuda_bf16.h>
#include <cstdint>

// Problem shape (fixed for this bench)
#define Bdim 128
#define Tdim 784
#define Kdim 512   // K of branch GEMMs
#define Hdim 512   // N of branch GEMMs
#define Odim 10
#define Mdim (Bdim * Tdim)   // 100352

// ---------------------------------------------------------------------------
// Scratch (device globals: allocation inside kernel_launch is forbidden)
// ---------------------------------------------------------------------------
__device__ float    g_d1[(size_t)Mdim * Hdim];
__device__ float    g_d2[(size_t)Mdim * Hdim];
__device__ uint32_t g_ballot[(size_t)Mdim * 16];   // 512 spikes -> 16 words per (b,t)
__device__ float    g_w1t[Kdim * Hdim];            // W1 transposed [K][N]
__device__ float    g_w2t[Kdim * Hdim];            // W2 transposed [K][N]

__device__ __forceinline__ uint32_t smem_u32(const void* p) {
    uint32_t a;
    asm("{ .reg .u64 t; cvta.to.shared.u64 t, %1; cvt.u32.u64 %0, t; }"
        : "=r"(a) : "l"(p));
    return a;
}

// Packed fp32x2 FMA; each lane is an IEEE fp32 RN FMA (bit-exact per chain).
#define FFMA2(d, a, b) \
    asm volatile("fma.rn.f32x2 %0, %1, %2, %0;" : "+l"(d) : "l"(a), "l"(b))
#define PACK2(out, lo, hi) \
    asm("mov.b64 %0, {%1, %2};" : "=l"(out) : "f"(lo), "f"(hi))
#define UNPACK2(lo, hi, in) \
    asm("mov.b64 {%0, %1}, %2;" : "=f"(lo), "=f"(hi) : "l"(in))

// ---------------------------------------------------------------------------
// Transpose: dst[C][R] = src[R][C]  (used only for W1/W2 — 1 MB each)
// ---------------------------------------------------------------------------
__global__ void __launch_bounds__(256) transpose_w_kernel(
    const float* __restrict__ W1, const float* __restrict__ W2)
{
    __shared__ float tile[32][33];
    const float* src = blockIdx.z ? W2 : W1;
    float* dst = blockIdx.z ? g_w2t : g_w1t;
    const int r0 = blockIdx.x * 32;
    const int c0 = blockIdx.y * 32;
    const int tx = threadIdx.x & 31;
    const int ty = threadIdx.x >> 5;   // 0..7
    #pragma unroll
    for (int j = 0; j < 4; j++)
        tile[ty + j * 8][tx] = src[(size_t)(r0 + ty + j * 8) * Kdim + c0 + tx];
    __syncthreads();
    #pragma unroll
    for (int j = 0; j < 4; j++)
        dst[(size_t)(c0 + ty + j * 8) * Hdim + r0 + tx] = tile[tx][ty + j * 8];
}

// ---------------------------------------------------------------------------
// Fused dual-branch GEMM: d1 = X@W1^T + b1 AND d2 = X@W2^T + b2 in one CTA.
//   Bit-exact fp32: ascending-k scalar IEEE FMA chain per output.
// ---------------------------------------------------------------------------
#define BK 16
#define LDSX 132                      // floats per k-row (128 data + 4 pad)
#define XBUF (BK * LDSX)              // 2112 floats per stage per matrix
#define NCHUNK (Kdim / BK)            // 32
#define SMEM_BYTES (6 * XBUF * 4)     // 2 stages x (X + W1 + W2) = 50688 B

#define CP16(s, g) \
    asm volatile("cp.async.cg.shared.global [%0], [%1], 16;" :: "r"(s), "l"(g) : "memory")

__global__ void __launch_bounds__(256, 1) gemm_fused_kernel(
    const float* __restrict__ X,
    const float* __restrict__ W1t, const float* __restrict__ b1,
    const float* __restrict__ W2t, const float* __restrict__ b2)
{
    extern __shared__ float sm[];
    float* Xs  = sm;                  // [2][BK][LDSX]  Xs[k][m]
    float* W1s = sm + 2 * XBUF;       // [2][BK][LDSX]  W1s[k][n]
    float* W2s = sm + 4 * XBUF;       // [2][BK][LDSX]  W2s[k][n]
    const uint32_t smbase = smem_u32(sm);

    const int tid  = threadIdx.x;
    const int lane = tid & 31;
    const int wid  = tid >> 5;
    const int mloc = (wid & 3) * 32 + (lane >> 3) * 8;   // thread row base
    const int nloc = (wid >> 2) * 64 + (lane & 7) * 8;   // thread col base

    const int n0 = blockIdx.x * 128;
    const int m0 = blockIdx.y * 128;

    // X loader mapping (row-major, coalesced): rows tid>>2 (+64), cols (tid&3)*4
    const int lrow = tid >> 2;
    const int lcol = (tid & 3) * 4;
    const float* xg = X + (size_t)(m0 + lrow) * Kdim + lcol;

    // W cp.async mapping: k-row = tid>>4 (0..15), float cols (tid&15)*4 and +64
    const int crow = tid >> 4;
    const int ccol = (tid & 15) * 4;
    const uint32_t cp_soff = (uint32_t)(crow * LDSX + ccol) * 4;
    const float* w1gp = W1t + (size_t)crow * Hdim + n0 + ccol;
    const float* w2gp = W2t + (size_t)crow * Hdim + n0 + ccol;

#define LDG_X(c) do {                                                        \
        xr[0] = *(const float4*)(xg + (c) * BK);                             \
        xr[1] = *(const float4*)(xg + (size_t)64 * Kdim + (c) * BK);         \
    } while (0)

#define STS_X(p) do {                                                        \
        _Pragma("unroll")                                                    \
        for (int _r = 0; _r < 2; _r++) {                                     \
            const float _xv[4] = {xr[_r].x, xr[_r].y, xr[_r].z, xr[_r].w};   \
            _Pragma("unroll")                                                \
            for (int _u = 0; _u < 4; _u++)                                   \
                Xs[(p) * XBUF + (lcol + _u) * LDSX + lrow + _r * 64] = _xv[_u]; \
        }                                                                    \
    } while (0)

#define CP_W(c, p) do {                                                      \
        const size_t _kw = (size_t)(c) * BK * Hdim;                          \
        const uint32_t _s1 = smbase + ((2 + (p)) * XBUF) * 4 + cp_soff;      \
        const uint32_t _s2 = smbase + ((4 + (p)) * XBUF) * 4 + cp_soff;      \
        CP16(_s1,       w1gp + _kw);                                         \
        CP16(_s1 + 256, w1gp + _kw + 64);                                    \
        CP16(_s2,       w2gp + _kw);                                         \
        CP16(_s2 + 256, w2gp + _kw + 64);                                    \
        asm volatile("cp.async.commit_group;" ::: "memory");                 \
    } while (0)

#define LDFRAG(buf, kk) do {                                                 \
        const float* _xr = xb  + (kk) * LDSX + mloc;                         \
        const float* _w1 = w1b + (kk) * LDSX + nloc;                         \
        const float* _w2 = w2b + (kk) * LDSX + nloc;                         \
        *(float4*)&fa[buf][0] = *(const float4*)_xr;                         \
        *(float4*)&fa[buf][4] = *(const float4*)(_xr + 4);                   \
        *(float4*)&f1[buf][0] = *(const float4*)_w1;                         \
        *(float4*)&f1[buf][4] = *(const float4*)(_w1 + 4);                   \
        *(float4*)&f2[buf][0] = *(const float4*)_w2;                         \
        *(float4*)&f2[buf][4] = *(const float4*)(_w2 + 4);                   \
    } while (0)

    float acc1[8][8], acc2[8][8];
    #pragma unroll
    for (int i = 0; i < 8; i++)
        #pragma unroll
        for (int j = 0; j < 8; j++) { acc1[i][j] = 0.f; acc2[i][j] = 0.f; }

    float4 xr[2];

    LDG_X(0);
    STS_X(0);
    CP_W(0, 0);
    LDG_X(1);

    for (int c = 0; c < NCHUNK; ++c) {
        const int p = c & 1;
        asm volatile("cp.async.wait_group 0;" ::: "memory");
        __syncthreads();

        if (c + 1 < NCHUNK) {
            STS_X(p ^ 1);
            CP_W(c + 1, p ^ 1);
        }
        if (c + 2 < NCHUNK) LDG_X(c + 2);

        const float* xb  = Xs  + p * XBUF;
        const float* w1b = W1s + p * XBUF;
        const float* w2b = W2s + p * XBUF;

        float fa[2][8], f1[2][8], f2[2][8];
        LDFRAG(0, 0);
        #pragma unroll
        for (int kk = 0; kk < BK; kk++) {
            const int cur = kk & 1;
            if (kk < BK - 1) LDFRAG(cur ^ 1, kk + 1);
            #pragma unroll
            for (int i = 0; i < 8; i++)
                #pragma unroll
                for (int j = 0; j < 8; j++) {
                    acc1[i][j] = fmaf(fa[cur][i], f1[cur][j], acc1[i][j]);
                    acc2[i][j] = fmaf(fa[cur][i], f2[cur][j], acc2[i][j]);
                }
        }
    }

    {
        const int nb = n0 + nloc;
        float bs1[8], bs2[8];
        #pragma unroll
        for (int j = 0; j < 8; j++) { bs1[j] = b1[nb + j]; bs2[j] = b2[nb + j]; }

        #pragma unroll
        for (int i = 0; i < 8; i++) {
            const int m = m0 + mloc + i;
            float* d1p = g_d1 + (size_t)m * Hdim + nb;
            float* d2p = g_d2 + (size_t)m * Hdim + nb;
            *(float4*)d1p = make_float4(acc1[i][0] + bs1[0], acc1[i][1] + bs1[1],
                                        acc1[i][2] + bs1[2], acc1[i][3] + bs1[3]);
            *(float4*)(d1p + 4) = make_float4(acc1[i][4] + bs1[4], acc1[i][5] + bs1[5],
                                              acc1[i][6] + bs1[6], acc1[i][7] + bs1[7]);
            *(float4*)d2p = make_float4(acc2[i][0] + bs2[0], acc2[i][1] + bs2[1],
                                        acc2[i][2] + bs2[2], acc2[i][3] + bs2[3]);
            *(float4*)(d2p + 4) = make_float4(acc2[i][4] + bs2[4], acc2[i][5] + bs2[5],
                                              acc2[i][6] + bs2[6], acc2[i][7] + bs2[7]);
        }
    }
}

// ---------------------------------------------------------------------------
// Kernel B: sequential LIF scan, software-pipelined in batches of 16 timesteps.
// 64-thread blocks (1024 blocks): near-perfect SM load balance.
// Recurrence statements textually identical -> bit-identical spikes.
// ---------------------------------------------------------------------------
__device__ __forceinline__ float sigmoidf(float x) { return 1.f / (1.f + expf(-x)); }

#define SB 16                         // timestep batch (784 = 16*49)

__global__ void __launch_bounds__(64) scan_kernel(
    const float* __restrict__ tau_m,
    const float* __restrict__ tau_n1,
    const float* __restrict__ tau_n2,
    const float* __restrict__ mem0,
    const float* __restrict__ spike0)
{
    const int tid = blockIdx.x * blockDim.x + threadIdx.x;
    const int b = tid / Hdim;
    const int h = tid - b * Hdim;
    const int lane = threadIdx.x & 31;

    const float alpha = sigmoidf(tau_m[h]);
    const float beta1 = sigmoidf(tau_n1[h]);
    const float beta2 = sigmoidf(tau_n2[h]);
    const float om_a = 1.f - alpha, om_b1 = 1.f - beta1, om_b2 = 1.f - beta2;

    float mem = mem0[tid];
    float spk = spike0[tid];
    float d1 = 0.f, d2 = 0.f;

    size_t base = ((size_t)b * Tdim) * Hdim + h;
    size_t bidx = ((size_t)b * Tdim) * 16 + (h >> 5);
    const float* __restrict__ D1 = g_d1;
    const float* __restrict__ D2 = g_d2;

    float pd1[SB], pd2[SB];
    #pragma unroll
    for (int j = 0; j < SB; j++) {
        pd1[j] = __ldcs(D1 + base + (size_t)j * Hdim);
        pd2[j] = __ldcs(D2 + base + (size_t)j * Hdim);
    }

    for (int tb = 0; tb < Tdim / SB; tb++) {
        float nd1[SB], nd2[SB];
        if (tb < Tdim / SB - 1) {
            #pragma unroll
            for (int j = 0; j < SB; j++) {
                nd1[j] = __ldcs(D1 + base + (size_t)(SB + j) * Hdim);
                nd2[j] = __ldcs(D2 + base + (size_t)(SB + j) * Hdim);
            }
        }
        #pragma unroll
        for (int j = 0; j < SB; j++) {
            float d1t = pd1[j];
            float d2t = pd2[j];
            d1 = beta1 * d1 + om_b1 * d1t;
            d2 = beta2 * d2 + om_b2 * d2t;
            mem = mem * alpha + om_a * (d1 + d2) - spk;   // V_TH = 1
            spk = (mem > 1.f) ? 1.f : 0.f;
            unsigned bal = __ballot_sync(0xffffffffu, mem > 1.f);
            if (lane == 0) g_ballot[bidx + (size_t)j * 16] = bal;
        }
        #pragma unroll
        for (int j = 0; j < SB; j++) { pd1[j] = nd1[j]; pd2[j] = nd2[j]; }
        base += (size_t)SB * Hdim;
        bidx += (size_t)SB * 16;
    }
}

// ---------------------------------------------------------------------------
// Kernel C: readout from spike ballots. Wr hoisted over rows; o-outputs packed
// in f32x2 pairs -> half the FMA issues (kernel is issue-bound, fma pipe ~32%).
// Each per-o accumulation chain has identical operands/order -> bit-identical.
// ---------------------------------------------------------------------------
#define ROWS_PER_WARP 8

__global__ void __launch_bounds__(256) readout_kernel(
    const float* __restrict__ Wr,
    const float* __restrict__ br,
    float* __restrict__ Out)
{
    __shared__ float WrS[Odim * Hdim];   // 20 KB
    __shared__ float brS[Odim];
    for (int i = threadIdx.x; i < Odim * Hdim; i += blockDim.x) WrS[i] = Wr[i];
    if (threadIdx.x < Odim) brS[threadIdx.x] = br[threadIdx.x];
    __syncthreads();

    const int warp = threadIdx.x >> 5;
    const int lane = threadIdx.x & 31;
    const int mbase = (blockIdx.x * 8 + warp) * ROWS_PER_WARP;

    // Stage 8 rows x 16 ballot words = 512B per warp, one uint4 per lane.
    const uint4 wv = *(const uint4*)(g_ballot + (size_t)mbase * 16 + lane * 4);
    uint32_t w[4] = {wv.x, wv.y, wv.z, wv.w};

    uint64_t acc[ROWS_PER_WARP][5];      // o-pairs (2o, 2o+1) packed
    #pragma unroll
    for (int g = 0; g < ROWS_PER_WARP; g++)
        #pragma unroll
        for (int q = 0; q < 5; q++) acc[g][q] = 0ull;

    #pragma unroll
    for (int j = 0; j < 16; j++) {               // h = j*32 + lane (ascending)
        const int hh = j * 32 + lane;
        uint64_t wp[5];
        #pragma unroll
        for (int q = 0; q < 5; q++) {
            const float lo = WrS[(2 * q) * Hdim + hh];
            const float hi = WrS[(2 * q + 1) * Hdim + hh];
            PACK2(wp[q], lo, hi);
        }

        #pragma unroll
        for (int g = 0; g < ROWS_PER_WARP; g++) {
            // word j of row g lives in lane g*4 + (j>>2), register j&3
            const uint32_t wjg = __shfl_sync(0xffffffffu, w[j & 3],
                                             g * 4 + (j >> 2));
            const float s = ((wjg >> lane) & 1u) ? 1.f : 0.f;
            uint64_t sp; PACK2(sp, s, s);
            #pragma unroll
            for (int q = 0; q < 5; q++)
                FFMA2(acc[g][q], sp, wp[q]);
        }
    }

    #pragma unroll
    for (int g = 0; g < ROWS_PER_WARP; g++) {
        float v[Odim];
        #pragma unroll
        for (int q = 0; q < 5; q++) UNPACK2(v[2 * q], v[2 * q + 1], acc[g][q]);
        #pragma unroll
        for (int o = 0; o < Odim; o++)
            #pragma unroll
            for (int d = 16; d; d >>= 1)
                v[o] += __shfl_xor_sync(0xffffffffu, v[o], d);
        if (lane == 0) {
            #pragma unroll
            for (int o = 0; o < Odim; o++)
                Out[(size_t)(mbase + g) * Odim + o] = v[o] + brS[o];
        }
    }
}

// ---------------------------------------------------------------------------
// Launch
// ---------------------------------------------------------------------------
extern "C" void kernel_launch(void* const* d_in, const int* in_sizes, int n_in,
                              void* d_out, int out_size)
{
    const float* input_data = (const float*)d_in[0];
    const float* W1     = (const float*)d_in[1];
    const float* b1     = (const float*)d_in[2];
    const float* W2     = (const float*)d_in[3];
    const float* b2     = (const float*)d_in[4];
    const float* tau_m  = (const float*)d_in[5];
    const float* tau_n1 = (const float*)d_in[6];
    const float* tau_n2 = (const float*)d_in[7];
    const float* Wr     = (const float*)d_in[8];
    const float* br     = (const float*)d_in[9];
    const float* mem0   = (const float*)d_in[10];
    const float* spike0 = (const float*)d_in[11];
    float* out = (float*)d_out;

    (void)in_sizes; (void)n_in; (void)out_size;

    float *w1t, *w2t;
    cudaGetSymbolAddress((void**)&w1t, g_w1t);
    cudaGetSymbolAddress((void**)&w2t, g_w2t);

    transpose_w_kernel<<<dim3(Hdim / 32, Kdim / 32, 2), 256>>>(W1, W2);

    cudaFuncSetAttribute(gemm_fused_kernel,
                         cudaFuncAttributeMaxDynamicSharedMemorySize, SMEM_BYTES);

    gemm_fused_kernel<<<dim3(Hdim / 128, Mdim / 128), 256, SMEM_BYTES>>>(
        input_data, w1t, b1, w2t, b2);

    scan_kernel<<<(Bdim * Hdim) / 64, 64>>>(tau_m, tau_n1, tau_n2, mem0, spike0);

    readout_kernel<<<Mdim / (8 * ROWS_PER_WARP), 256>>>(Wr, br, out);
}